// round 1
// baseline (speedup 1.0000x reference)
#include <cuda_runtime.h>
#include <math.h>

#define FFT_N  16384
#define SEQ_L  8192
#define NCH    1024
#define NPAIR  512          // channel pairs
#define NBATCH 4
#define BT     512          // threads per block
#define TW_SIZE 12288       // 3N/4 twiddles
#define SMEM_BYTES (2 * FFT_N * 4)   // re[] + im[] fp32 = 128 KB

#ifndef M_PI
#define M_PI 3.14159265358979323846
#endif

// -------- device globals (static allocation only — no cudaMalloc allowed) ----
__device__ float2 g_tw[TW_SIZE];                       // exp(-2*pi*i*j/N)
__device__ float2 g_kf[(size_t)NPAIR * FFT_N];          // packed filter spectra
                                                        // (digit-reversed order)

// digit-reverse base-4 of a 14-bit index (7 digits). Self-inverse.
__device__ __forceinline__ int drev14(int p) {
    unsigned r = __brev((unsigned)p) >> 18;             // 14-bit bit reversal
    return (int)(((r & 0x1555u) << 1) | ((r & 0x2AAAu) >> 1));
}

// ---- in-place radix-4 DIF forward FFT: natural in -> digit-reversed out ----
__device__ __forceinline__ void fft4_fwd(float* re, float* im) {
    for (int lm = 12; lm >= 0; lm -= 2) {
        const int m = 1 << lm;
        #pragma unroll 4
        for (int idx = threadIdx.x; idx < FFT_N / 4; idx += BT) {
            const int j = idx & (m - 1);
            const int i = ((idx >> lm) << (lm + 2)) + j;
            float ar = re[i],         ai = im[i];
            float br = re[i + m],     bi = im[i + m];
            float cr = re[i + 2*m],   ci = im[i + 2*m];
            float dr = re[i + 3*m],   di = im[i + 3*m];
            float t0r = ar + cr, t0i = ai + ci;
            float t1r = ar - cr, t1i = ai - ci;
            float t2r = br + dr, t2i = bi + di;
            float t3r = bi - di, t3i = dr - br;          // -i*(b-d)
            const int twi = j << (12 - lm);              // j * N/(4m)
            float2 w1 = g_tw[twi];
            float2 w2 = g_tw[2 * twi];
            float2 w3 = g_tw[3 * twi];
            re[i]       = t0r + t2r;  im[i]       = t0i + t2i;
            float o1r = t1r + t3r, o1i = t1i + t3i;
            re[i + m]   = o1r * w1.x - o1i * w1.y;
            im[i + m]   = o1r * w1.y + o1i * w1.x;
            float o2r = t0r - t2r, o2i = t0i - t2i;
            re[i + 2*m] = o2r * w2.x - o2i * w2.y;
            im[i + 2*m] = o2r * w2.y + o2i * w2.x;
            float o3r = t1r - t3r, o3i = t1i - t3i;
            re[i + 3*m] = o3r * w3.x - o3i * w3.y;
            im[i + 3*m] = o3r * w3.y + o3i * w3.x;
        }
        __syncthreads();
    }
}

// ---- in-place radix-4 DIT inverse FFT (unnormalized, conj twiddles):
//      digit-reversed in -> natural out ----
__device__ __forceinline__ void fft4_inv(float* re, float* im) {
    for (int lm = 0; lm <= 12; lm += 2) {
        const int m = 1 << lm;
        #pragma unroll 4
        for (int idx = threadIdx.x; idx < FFT_N / 4; idx += BT) {
            const int j = idx & (m - 1);
            const int i = ((idx >> lm) << (lm + 2)) + j;
            const int twi = j << (12 - lm);
            float2 w1 = g_tw[twi];
            float2 w2 = g_tw[2 * twi];
            float2 w3 = g_tw[3 * twi];
            float a0r = re[i],         a0i = im[i];
            float a1r = re[i + m],     a1i = im[i + m];
            float a2r = re[i + 2*m],   a2i = im[i + 2*m];
            float a3r = re[i + 3*m],   a3i = im[i + 3*m];
            // b_k = A_k * conj(w_k)
            float b1r = a1r * w1.x + a1i * w1.y, b1i = a1i * w1.x - a1r * w1.y;
            float b2r = a2r * w2.x + a2i * w2.y, b2i = a2i * w2.x - a2r * w2.y;
            float b3r = a3r * w3.x + a3i * w3.y, b3i = a3i * w3.x - a3r * w3.y;
            float u0r = a0r + b2r, u0i = a0i + b2i;
            float u1r = a0r - b2r, u1i = a0i - b2i;
            float u2r = b1r + b3r, u2i = b1i + b3i;
            float u3r = b3i - b1i, u3i = b1r - b3r;      // +i*(b1-b3)
            re[i]       = u0r + u2r;  im[i]       = u0i + u2i;
            re[i + m]   = u1r + u3r;  im[i + m]   = u1i + u3i;
            re[i + 2*m] = u0r - u2r;  im[i + 2*m] = u0i - u2i;
            re[i + 3*m] = u1r - u3r;  im[i + 3*m] = u1i - u3i;
        }
        __syncthreads();
    }
}

// ---------------- twiddle init (double precision, every launch) -------------
__global__ void k_twinit() {
    int j = blockIdx.x * blockDim.x + threadIdx.x;
    if (j < TW_SIZE) {
        double a = -2.0 * M_PI * (double)j / (double)FFT_N;
        g_tw[j] = make_float2((float)cos(a), (float)sin(a));
    }
}

// ------------- filter spectra: pack (2c, 2c+1) -> complex, FFT --------------
__global__ void __launch_bounds__(BT, 1) k_filt(const float* __restrict__ filt) {
    extern __shared__ float sm[];
    float* re = sm;
    float* im = sm + FFT_N;
    const int c = blockIdx.x;                       // 0..NPAIR-1
    const float* k0 = filt + (size_t)(2 * c)     * SEQ_L;
    const float* k1 = filt + (size_t)(2 * c + 1) * SEQ_L;
    for (int t = threadIdx.x; t < SEQ_L; t += BT) { re[t] = k0[t]; im[t] = k1[t]; }
    for (int t = SEQ_L + threadIdx.x; t < FFT_N; t += BT) { re[t] = 0.f; im[t] = 0.f; }
    __syncthreads();
    fft4_fwd(re, im);
    float2* out = g_kf + (size_t)c * FFT_N;
    for (int p = threadIdx.x; p < FFT_N; p += BT)
        out[p] = make_float2(re[p], im[p]);         // store digit-reversed order
}

// ------------------------------- main conv ----------------------------------
// One block per (batch, channel-pair). x viewed as float2 rows of width 512.
__global__ void __launch_bounds__(BT, 1) k_conv(const float2* __restrict__ x2,
                                                float2* __restrict__ y2) {
    extern __shared__ float sm[];
    float* re = sm;
    float* im = sm + FFT_N;
    const int b = blockIdx.x & 3;                   // 4 consecutive blocks share c's kf
    const int c = blockIdx.x >> 2;

    const float2* xr = x2 + (size_t)b * SEQ_L * NPAIR + c;
    for (int t = threadIdx.x; t < SEQ_L; t += BT) {
        float2 v = xr[(size_t)t * NPAIR];
        re[t] = v.x; im[t] = v.y;
    }
    for (int t = SEQ_L + threadIdx.x; t < FFT_N; t += BT) { re[t] = 0.f; im[t] = 0.f; }
    __syncthreads();

    fft4_fwd(re, im);

    // Pointwise multiply with conjugate-symmetry unpack/repack.
    // Storage position p holds Z[f], f = drev14(p). Process each (f, N-f) pair once.
    const float2* kf = g_kf + (size_t)c * FFT_N;
    const float scale = 1.0f / (4.0f * (float)FFT_N);
    for (int p = threadIdx.x; p < FFT_N; p += BT) {
        const int f = drev14(p);
        if (f > FFT_N / 2) continue;
        const int q  = (FFT_N - f) & (FFT_N - 1);
        const int p2 = drev14(q);
        float ar = re[p],   ai = im[p];
        float br = re[p2],  bi = -im[p2];           // conj Z[N-f]
        float2 C  = kf[p];
        float2 Dv = kf[p2];
        float cr = C.x,  ci = C.y;
        float dr = Dv.x, di = -Dv.y;                // conj Zk[N-f]
        float apbr = ar + br, apbi = ai + bi;
        float ambr = ar - br, ambi = ai - bi;
        float cpdr = cr + dr, cpdi = ci + di;
        float cmdr = cr - dr, cmdi = ci - di;
        float Pr = apbr * cpdr - apbi * cpdi, Pi = apbr * cpdi + apbi * cpdr;
        float Qr = ambr * cmdr - ambi * cmdi, Qi = ambr * cmdi + ambi * cmdr;
        // W[f]   = (P - i*Q)/(4N),  W[N-f] = conj(P + i*Q)/(4N)
        re[p]  = (Pr + Qi) * scale;
        im[p]  = (Pi - Qr) * scale;
        re[p2] = (Pr - Qi) * scale;
        im[p2] = -(Pi + Qr) * scale;
    }
    __syncthreads();

    fft4_inv(re, im);

    float2* yr = y2 + (size_t)b * SEQ_L * NPAIR + c;
    for (int t = threadIdx.x; t < SEQ_L; t += BT)
        yr[(size_t)t * NPAIR] = make_float2(re[t], im[t]);
}

// ------------------------------ launch --------------------------------------
extern "C" void kernel_launch(void* const* d_in, const int* in_sizes, int n_in,
                              void* d_out, int out_size) {
    const float* x    = (const float*)d_in[0];
    const float* filt = (const float*)d_in[1];
    // defensive: identify by size (x has 33.5M elems, filt 8.4M)
    if (n_in >= 2 && in_sizes[0] == NCH * SEQ_L && in_sizes[1] == NBATCH * SEQ_L * NCH) {
        const float* t = x; x = filt; filt = t;
    }
    float* out = (float*)d_out;

    cudaFuncSetAttribute(k_filt, cudaFuncAttributeMaxDynamicSharedMemorySize, SMEM_BYTES);
    cudaFuncSetAttribute(k_conv, cudaFuncAttributeMaxDynamicSharedMemorySize, SMEM_BYTES);

    k_twinit<<<(TW_SIZE + 255) / 256, 256>>>();
    k_filt<<<NPAIR, BT, SMEM_BYTES>>>(filt);
    k_conv<<<NBATCH * NPAIR, BT, SMEM_BYTES>>>((const float2*)x, (float2*)out);
}

// round 2
// speedup vs baseline: 1.9018x; 1.9018x over previous
#include <cuda_runtime.h>
#include <math.h>

#define FFT_N  16384
#define SEQ_L  8192
#define NCH    1024
#define NPAIR  512
#define NBATCH 4
#define BT     512
#define TW_SIZE 1024                       // only W_16384^r, r<1024 needed
#define SM_FLOATS (FFT_N + (FFT_N >> 5))   // padded: 16896
#define SMEM_BYTES (2 * SM_FLOATS * 4)     // 135168 B

#ifndef M_PI
#define M_PI 3.14159265358979323846
#endif

#define SP(i) ((i) + ((i) >> 5))

// -------- device globals (no cudaMalloc allowed) ----------------------------
__device__ float2 g_tw[TW_SIZE];                  // exp(-2*pi*i*r/N), r<1024
__device__ float2 g_kf[(size_t)NPAIR * FFT_N];    // filter spectra (digit-rev)

// digit-reverse base-4 of a 14-bit index (7 digits). Self-inverse.
__device__ __forceinline__ int drev14(int p) {
    unsigned r = __brev((unsigned)p) >> 18;
    return (int)(((r & 0x1555u) << 1) | ((r & 0x2AAAu) >> 1));
}

// ----------------------------- complex helpers ------------------------------
struct C2 { float x, y; };
__device__ __forceinline__ C2 mkc(float a, float b){ C2 r; r.x=a; r.y=b; return r; }
__device__ __forceinline__ C2 cadd(C2 a, C2 b){ return mkc(a.x+b.x, a.y+b.y); }
__device__ __forceinline__ C2 csub(C2 a, C2 b){ return mkc(a.x-b.x, a.y-b.y); }
__device__ __forceinline__ C2 cmul(C2 a, C2 b){ return mkc(a.x*b.x - a.y*b.y, a.x*b.y + a.y*b.x); }
__device__ __forceinline__ C2 cmulc(C2 a, C2 b){ return mkc(a.x*b.x + a.y*b.y, a.y*b.x - a.x*b.y); } // a*conj(b)
__device__ __forceinline__ C2 mulni(C2 a){ return mkc(a.y, -a.x); }  // -i*a
__device__ __forceinline__ C2 mulpi(C2 a){ return mkc(-a.y, a.x); }  // +i*a

// w16^n = cos(2pi n/16) - i sin(2pi n/16), n = 0..9 (constant-folded when n literal)
__device__ __forceinline__ C2 w16c(int n) {
    const float C[10] = {1.f, 0.92387953f, 0.70710678f, 0.38268343f, 0.f,
                         -0.38268343f, -0.70710678f, -0.92387953f, -1.f, -0.92387953f};
    const float S[10] = {0.f, -0.38268343f, -0.70710678f, -0.92387953f, -1.f,
                         -0.92387953f, -0.70710678f, -0.38268343f, 0.f, 0.38268343f};
    return mkc(C[n], S[n]);
}

// ---------------- register radix-16 (two fused radix-4 DIF layers) ----------
// In-place on v[j] = data[i0 + j*m]; u1 = W_{16m}^r where r = i0 mod m.
__device__ __forceinline__ void r16_fwd(C2* v, C2 u1) {
    C2 u2 = cmul(u1,u1);
    C2 u3 = cmul(u2,u1);
    C2 u4 = cmul(u2,u2);
    C2 u8 = cmul(u4,u4);
    C2 u12 = cmul(u8,u4);
    #pragma unroll
    for (int q = 0; q < 4; q++) {        // layer 1: stride 4m
        C2 a=v[q], b=v[q+4], c=v[q+8], d=v[q+12];
        C2 t0=cadd(a,c), t1=csub(a,c), t2=cadd(b,d), t3=mulni(csub(b,d));
        v[q] = cadd(t0,t2);
        C2 o1 = cmul(cadd(t1,t3), u1);
        C2 o2 = cmul(csub(t0,t2), u2);
        C2 o3 = cmul(csub(t1,t3), u3);
        if (q) {
            o1 = cmul(o1, w16c(q));
            o2 = cmul(o2, w16c(2*q));
            o3 = cmul(o3, w16c(3*q));
        }
        v[q+4]=o1; v[q+8]=o2; v[q+12]=o3;
    }
    #pragma unroll
    for (int s = 0; s < 4; s++) {        // layer 2: stride m
        C2 a=v[4*s], b=v[4*s+1], c=v[4*s+2], d=v[4*s+3];
        C2 t0=cadd(a,c), t1=csub(a,c), t2=cadd(b,d), t3=mulni(csub(b,d));
        v[4*s]   = cadd(t0,t2);
        v[4*s+1] = cmul(cadd(t1,t3), u4);
        v[4*s+2] = cmul(csub(t0,t2), u8);
        v[4*s+3] = cmul(csub(t1,t3), u12);
    }
}

// Inverse: two fused radix-4 DIT layers (conjugate twiddles applied on inputs)
__device__ __forceinline__ void r16_inv(C2* v, C2 u1) {
    C2 u2 = cmul(u1,u1);
    C2 u3 = cmul(u2,u1);
    C2 u4 = cmul(u2,u2);
    C2 u8 = cmul(u4,u4);
    C2 u12 = cmul(u8,u4);
    #pragma unroll
    for (int s = 0; s < 4; s++) {        // layer 1: stride m
        C2 a = v[4*s];
        C2 b = cmulc(v[4*s+1], u4);
        C2 c = cmulc(v[4*s+2], u8);
        C2 d = cmulc(v[4*s+3], u12);
        C2 p0=cadd(a,c), p1=csub(a,c), p2=cadd(b,d), p3=mulpi(csub(b,d));
        v[4*s]=cadd(p0,p2); v[4*s+1]=cadd(p1,p3); v[4*s+2]=csub(p0,p2); v[4*s+3]=csub(p1,p3);
    }
    #pragma unroll
    for (int q = 0; q < 4; q++) {        // layer 2: stride 4m
        C2 a = v[q];
        C2 b = cmulc(v[q+4],  u1);
        C2 c = cmulc(v[q+8],  u2);
        C2 d = cmulc(v[q+12], u3);
        if (q) {
            b = cmulc(b, w16c(q));
            c = cmulc(c, w16c(2*q));
            d = cmulc(d, w16c(3*q));
        }
        C2 p0=cadd(a,c), p1=csub(a,c), p2=cadd(b,d), p3=mulpi(csub(b,d));
        v[q]=cadd(p0,p2); v[q+4]=cadd(p1,p3); v[q+8]=csub(p0,p2); v[q+12]=csub(p1,p3);
    }
}

// ------------------------------ shared passes -------------------------------
template<int LM>
__device__ __forceinline__ void pass16_fwd(float* re, float* im) {
    const int m = 1 << LM;
    #pragma unroll
    for (int w = 0; w < 2; w++) {
        const int bf = threadIdx.x + w * BT;
        const int r = bf & (m - 1);
        const int i0 = ((bf >> LM) << (LM + 4)) + r;
        float2 uu = g_tw[r << (10 - LM)];
        C2 u1 = mkc(uu.x, uu.y);
        C2 v[16];
        #pragma unroll
        for (int j = 0; j < 16; j++) { int a = SP(i0 + j*m); v[j] = mkc(re[a], im[a]); }
        r16_fwd(v, u1);
        #pragma unroll
        for (int j = 0; j < 16; j++) { int a = SP(i0 + j*m); re[a] = v[j].x; im[a] = v[j].y; }
    }
    __syncthreads();
}

template<int LM>
__device__ __forceinline__ void pass16_inv(float* re, float* im) {
    const int m = 1 << LM;
    #pragma unroll
    for (int w = 0; w < 2; w++) {
        const int bf = threadIdx.x + w * BT;
        const int r = bf & (m - 1);
        const int i0 = ((bf >> LM) << (LM + 4)) + r;
        float2 uu = g_tw[r << (10 - LM)];
        C2 u1 = mkc(uu.x, uu.y);
        C2 v[16];
        #pragma unroll
        for (int j = 0; j < 16; j++) { int a = SP(i0 + j*m); v[j] = mkc(re[a], im[a]); }
        r16_inv(v, u1);
        #pragma unroll
        for (int j = 0; j < 16; j++) { int a = SP(i0 + j*m); re[a] = v[j].x; im[a] = v[j].y; }
    }
    __syncthreads();
}

__device__ __forceinline__ void pass4_fwd(float* re, float* im) {
    #pragma unroll
    for (int w = 0; w < 8; w++) {
        const int i = 4 * (threadIdx.x + w * BT);
        int a0=SP(i), a1=SP(i+1), a2=SP(i+2), a3=SP(i+3);
        C2 a=mkc(re[a0],im[a0]), b=mkc(re[a1],im[a1]);
        C2 c=mkc(re[a2],im[a2]), d=mkc(re[a3],im[a3]);
        C2 t0=cadd(a,c), t1=csub(a,c), t2=cadd(b,d), t3=mulni(csub(b,d));
        C2 o0=cadd(t0,t2), o1=cadd(t1,t3), o2=csub(t0,t2), o3=csub(t1,t3);
        re[a0]=o0.x; im[a0]=o0.y; re[a1]=o1.x; im[a1]=o1.y;
        re[a2]=o2.x; im[a2]=o2.y; re[a3]=o3.x; im[a3]=o3.y;
    }
    __syncthreads();
}

__device__ __forceinline__ void pass4_inv(float* re, float* im) {
    #pragma unroll
    for (int w = 0; w < 8; w++) {
        const int i = 4 * (threadIdx.x + w * BT);
        int a0=SP(i), a1=SP(i+1), a2=SP(i+2), a3=SP(i+3);
        C2 a=mkc(re[a0],im[a0]), b=mkc(re[a1],im[a1]);
        C2 c=mkc(re[a2],im[a2]), d=mkc(re[a3],im[a3]);
        C2 p0=cadd(a,c), p1=csub(a,c), p2=cadd(b,d), p3=mulpi(csub(b,d));
        C2 o0=cadd(p0,p2), o1=cadd(p1,p3), o2=csub(p0,p2), o3=csub(p1,p3);
        re[a0]=o0.x; im[a0]=o0.y; re[a1]=o1.x; im[a1]=o1.y;
        re[a2]=o2.x; im[a2]=o2.y; re[a3]=o3.x; im[a3]=o3.y;
    }
    __syncthreads();
}

// natural in -> digit-reversed out
__device__ __forceinline__ void fft_fwd(float* re, float* im) {
    pass16_fwd<10>(re, im);
    pass16_fwd<6>(re, im);
    pass16_fwd<2>(re, im);
    pass4_fwd(re, im);
}
// digit-reversed in -> natural out (unnormalized)
__device__ __forceinline__ void fft_inv(float* re, float* im) {
    pass4_inv(re, im);
    pass16_inv<2>(re, im);
    pass16_inv<6>(re, im);
    pass16_inv<10>(re, im);
}

// ---------------- twiddle init (double precision, every launch) -------------
__global__ void k_twinit() {
    int j = blockIdx.x * blockDim.x + threadIdx.x;
    if (j < TW_SIZE) {
        double a = -2.0 * M_PI * (double)j / (double)FFT_N;
        g_tw[j] = make_float2((float)cos(a), (float)sin(a));
    }
}

// ------------- filter spectra: pack (2c, 2c+1) -> complex, FFT --------------
__global__ void __launch_bounds__(BT) k_filt(const float* __restrict__ filt) {
    extern __shared__ float sm[];
    float* re = sm;
    float* im = sm + SM_FLOATS;
    const int c = blockIdx.x;
    const float* k0 = filt + (size_t)(2 * c)     * SEQ_L;
    const float* k1 = filt + (size_t)(2 * c + 1) * SEQ_L;
    for (int t = threadIdx.x; t < SEQ_L; t += BT) { re[SP(t)] = k0[t]; im[SP(t)] = k1[t]; }
    for (int t = SEQ_L + threadIdx.x; t < FFT_N; t += BT) { re[SP(t)] = 0.f; im[SP(t)] = 0.f; }
    __syncthreads();
    fft_fwd(re, im);
    float2* out = g_kf + (size_t)c * FFT_N;
    for (int p = threadIdx.x; p < FFT_N; p += BT)
        out[p] = make_float2(re[SP(p)], im[SP(p)]);
}

// ------------------------------- main conv ----------------------------------
__global__ void __launch_bounds__(BT) k_conv(const float2* __restrict__ x2,
                                             float2* __restrict__ y2) {
    extern __shared__ float sm[];
    float* re = sm;
    float* im = sm + SM_FLOATS;
    const int b = blockIdx.x & 3;
    const int c = blockIdx.x >> 2;

    const float2* xr = x2 + (size_t)b * SEQ_L * NPAIR + c;
    for (int t = threadIdx.x; t < SEQ_L; t += BT) {
        float2 v = xr[(size_t)t * NPAIR];
        re[SP(t)] = v.x; im[SP(t)] = v.y;
    }
    for (int t = SEQ_L + threadIdx.x; t < FFT_N; t += BT) { re[SP(t)] = 0.f; im[SP(t)] = 0.f; }
    __syncthreads();

    fft_fwd(re, im);

    // Pointwise multiply with conjugate-symmetry unpack/repack.
    // Iterate frequencies f = 0..N/2; storage position of f is drev14(f).
    const float2* kf = g_kf + (size_t)c * FFT_N;
    const float scale = 1.0f / (4.0f * (float)FFT_N);
    for (int f = threadIdx.x; f <= FFT_N / 2; f += BT) {
        const int p  = drev14(f);
        const int q  = (FFT_N - f) & (FFT_N - 1);
        const int p2 = drev14(q);
        const int sp = SP(p), sp2 = SP(p2);
        float ar = re[sp],   ai = im[sp];
        float br = re[sp2],  bi = -im[sp2];
        float2 Cv = kf[p];
        float2 Dv = kf[p2];
        float cr = Cv.x,  ci = Cv.y;
        float dr = Dv.x,  di = -Dv.y;
        float apbr = ar + br, apbi = ai + bi;
        float ambr = ar - br, ambi = ai - bi;
        float cpdr = cr + dr, cpdi = ci + di;
        float cmdr = cr - dr, cmdi = ci - di;
        float Pr = apbr * cpdr - apbi * cpdi, Pi = apbr * cpdi + apbi * cpdr;
        float Qr = ambr * cmdr - ambi * cmdi, Qi = ambr * cmdi + ambi * cmdr;
        re[sp]  = (Pr + Qi) * scale;
        im[sp]  = (Pi - Qr) * scale;
        re[sp2] = (Pr - Qi) * scale;
        im[sp2] = -(Pi + Qr) * scale;
    }
    __syncthreads();

    fft_inv(re, im);

    float2* yr = y2 + (size_t)b * SEQ_L * NPAIR + c;
    for (int t = threadIdx.x; t < SEQ_L; t += BT)
        yr[(size_t)t * NPAIR] = make_float2(re[SP(t)], im[SP(t)]);
}

// ------------------------------ launch --------------------------------------
extern "C" void kernel_launch(void* const* d_in, const int* in_sizes, int n_in,
                              void* d_out, int out_size) {
    const float* x    = (const float*)d_in[0];
    const float* filt = (const float*)d_in[1];
    if (n_in >= 2 && in_sizes[0] == NCH * SEQ_L && in_sizes[1] == NBATCH * SEQ_L * NCH) {
        const float* t = x; x = filt; filt = t;
    }
    float* out = (float*)d_out;

    cudaFuncSetAttribute(k_filt, cudaFuncAttributeMaxDynamicSharedMemorySize, SMEM_BYTES);
    cudaFuncSetAttribute(k_conv, cudaFuncAttributeMaxDynamicSharedMemorySize, SMEM_BYTES);

    k_twinit<<<(TW_SIZE + 255) / 256, 256>>>();
    k_filt<<<NPAIR, BT, SMEM_BYTES>>>(filt);
    k_conv<<<NBATCH * NPAIR, BT, SMEM_BYTES>>>((const float2*)x, (float2*)out);
}

// round 3
// speedup vs baseline: 2.4762x; 1.3020x over previous
#include <cuda_runtime.h>
#include <math.h>

#define FFT_N   16384
#define SEQ_L   8192
#define NCH     1024
#define NPAIR   512
#define NBATCH  4
#define BT      1024
#define TW_SIZE 1024
#define KF_STRIDE 8256                    // >= 8193, 64-aligned
#define SM2 (FFT_N + (FFT_N >> 4))        // 17408 float2 (padded)
#define SMEM_BYTES (SM2 * 8)              // 139264 B

#ifndef M_PI
#define M_PI 3.14159265358979323846
#endif

#define SP2(i) ((i) + ((i) >> 4))

// -------- device globals (no cudaMalloc allowed) ----------------------------
__device__ float2 g_tw[TW_SIZE];                      // W_N^r, r<1024
__device__ float4 g_kf[(size_t)NPAIR * KF_STRIDE];    // (Zk[f], Zk[N-f]) pairs

// digit-reverse base-4 of a 14-bit index. Self-inverse.
__device__ __forceinline__ int drev14(int p) {
    unsigned r = __brev((unsigned)p) >> 18;
    return (int)(((r & 0x1555u) << 1) | ((r & 0x2AAAu) >> 1));
}

// ----------------------------- complex helpers ------------------------------
struct C2 { float x, y; };
__device__ __forceinline__ C2 mkc(float a, float b){ C2 r; r.x=a; r.y=b; return r; }
__device__ __forceinline__ C2 cadd(C2 a, C2 b){ return mkc(a.x+b.x, a.y+b.y); }
__device__ __forceinline__ C2 csub(C2 a, C2 b){ return mkc(a.x-b.x, a.y-b.y); }
__device__ __forceinline__ C2 cmul(C2 a, C2 b){ return mkc(a.x*b.x - a.y*b.y, a.x*b.y + a.y*b.x); }
__device__ __forceinline__ C2 cmulc(C2 a, C2 b){ return mkc(a.x*b.x + a.y*b.y, a.y*b.x - a.x*b.y); } // a*conj(b)
__device__ __forceinline__ C2 mulni(C2 a){ return mkc(a.y, -a.x); }  // -i*a
__device__ __forceinline__ C2 mulpi(C2 a){ return mkc(-a.y, a.x); }  // +i*a

__device__ __forceinline__ C2 w16c(int n) {   // W_16^n (n literal -> folded)
    const float C[10] = {1.f, 0.92387953f, 0.70710678f, 0.38268343f, 0.f,
                         -0.38268343f, -0.70710678f, -0.92387953f, -1.f, -0.92387953f};
    const float S[10] = {0.f, -0.38268343f, -0.70710678f, -0.92387953f, -1.f,
                         -0.92387953f, -0.70710678f, -0.38268343f, 0.f, 0.38268343f};
    return mkc(C[n], S[n]);
}

// ---------------- register radix-16 (two fused radix-4 layers) --------------
__device__ __forceinline__ void r16_fwd(C2* v, C2 u1) {
    C2 u2 = cmul(u1,u1);
    C2 u3 = cmul(u2,u1);
    #pragma unroll
    for (int q = 0; q < 4; q++) {          // layer 1: stride 4m
        C2 a=v[q], b=v[q+4], c=v[q+8], d=v[q+12];
        C2 t0=cadd(a,c), t1=csub(a,c), t2=cadd(b,d), t3=mulni(csub(b,d));
        v[q] = cadd(t0,t2);
        C2 o1 = cmul(cadd(t1,t3), u1);
        C2 o2 = cmul(csub(t0,t2), u2);
        C2 o3 = cmul(csub(t1,t3), u3);
        if (q) { o1=cmul(o1,w16c(q)); o2=cmul(o2,w16c(2*q)); o3=cmul(o3,w16c(3*q)); }
        v[q+4]=o1; v[q+8]=o2; v[q+12]=o3;
    }
    C2 u4 = cmul(u2,u2);
    C2 u8 = cmul(u4,u4);
    C2 u12 = cmul(u8,u4);
    #pragma unroll
    for (int s = 0; s < 4; s++) {          // layer 2: stride m
        C2 a=v[4*s], b=v[4*s+1], c=v[4*s+2], d=v[4*s+3];
        C2 t0=cadd(a,c), t1=csub(a,c), t2=cadd(b,d), t3=mulni(csub(b,d));
        v[4*s]   = cadd(t0,t2);
        v[4*s+1] = cmul(cadd(t1,t3), u4);
        v[4*s+2] = cmul(csub(t0,t2), u8);
        v[4*s+3] = cmul(csub(t1,t3), u12);
    }
}

// forward layers with v[8..15] == 0 (zero-padded input folded)
__device__ __forceinline__ void r16_fwd_zfold(C2* v, C2 u1) {
    C2 u2 = cmul(u1,u1);
    C2 u3 = cmul(u2,u1);
    #pragma unroll
    for (int q = 0; q < 4; q++) {          // layer 1 with c=d=0
        C2 a=v[q], b=v[q+4];
        C2 nb = mulni(b);
        C2 o0 = cadd(a,b);
        C2 o1 = cmul(cadd(a,nb), u1);
        C2 o2 = cmul(csub(a,b), u2);
        C2 o3 = cmul(csub(a,nb), u3);
        if (q) { o1=cmul(o1,w16c(q)); o2=cmul(o2,w16c(2*q)); o3=cmul(o3,w16c(3*q)); }
        v[q]=o0; v[q+4]=o1; v[q+8]=o2; v[q+12]=o3;
    }
    C2 u4 = cmul(u2,u2);
    C2 u8 = cmul(u4,u4);
    C2 u12 = cmul(u8,u4);
    #pragma unroll
    for (int s = 0; s < 4; s++) {          // layer 2 standard
        C2 a=v[4*s], b=v[4*s+1], c=v[4*s+2], d=v[4*s+3];
        C2 t0=cadd(a,c), t1=csub(a,c), t2=cadd(b,d), t3=mulni(csub(b,d));
        v[4*s]   = cadd(t0,t2);
        v[4*s+1] = cmul(cadd(t1,t3), u4);
        v[4*s+2] = cmul(csub(t0,t2), u8);
        v[4*s+3] = cmul(csub(t1,t3), u12);
    }
}

__device__ __forceinline__ void r16_inv(C2* v, C2 u1) {
    C2 u2 = cmul(u1,u1);
    C2 u4 = cmul(u2,u2);
    C2 u8 = cmul(u4,u4);
    C2 u12 = cmul(u8,u4);
    #pragma unroll
    for (int s = 0; s < 4; s++) {          // layer 1: stride m
        C2 a = v[4*s];
        C2 b = cmulc(v[4*s+1], u4);
        C2 c = cmulc(v[4*s+2], u8);
        C2 d = cmulc(v[4*s+3], u12);
        C2 p0=cadd(a,c), p1=csub(a,c), p2=cadd(b,d), p3=mulpi(csub(b,d));
        v[4*s]=cadd(p0,p2); v[4*s+1]=cadd(p1,p3); v[4*s+2]=csub(p0,p2); v[4*s+3]=csub(p1,p3);
    }
    C2 u3 = cmul(u2,u1);
    #pragma unroll
    for (int q = 0; q < 4; q++) {          // layer 2: stride 4m
        C2 a = v[q];
        C2 b = cmulc(v[q+4],  u1);
        C2 c = cmulc(v[q+8],  u2);
        C2 d = cmulc(v[q+12], u3);
        if (q) { b=cmulc(b,w16c(q)); c=cmulc(c,w16c(2*q)); d=cmulc(d,w16c(3*q)); }
        C2 p0=cadd(a,c), p1=csub(a,c), p2=cadd(b,d), p3=mulpi(csub(b,d));
        v[q]=cadd(p0,p2); v[q+4]=cadd(p1,p3); v[q+8]=csub(p0,p2); v[q+12]=csub(p1,p3);
    }
}

// ------------------------------ shared passes -------------------------------
template<int LM>
__device__ __forceinline__ void pass16_fwd(float2* cs) {
    const int m = 1 << LM;
    const int bf = threadIdx.x;
    const int r = bf & (m - 1);
    const int i0 = ((bf >> LM) << (LM + 4)) + r;
    float2 uu = g_tw[r << (10 - LM)];
    C2 u1 = mkc(uu.x, uu.y);
    C2 v[16];
    #pragma unroll
    for (int j = 0; j < 16; j++) { float2 t = cs[SP2(i0 + j*m)]; v[j] = mkc(t.x, t.y); }
    r16_fwd(v, u1);
    #pragma unroll
    for (int j = 0; j < 16; j++) cs[SP2(i0 + j*m)] = make_float2(v[j].x, v[j].y);
    __syncthreads();
}

template<int LM>
__device__ __forceinline__ void pass16_inv(float2* cs) {
    const int m = 1 << LM;
    const int bf = threadIdx.x;
    const int r = bf & (m - 1);
    const int i0 = ((bf >> LM) << (LM + 4)) + r;
    float2 uu = g_tw[r << (10 - LM)];
    C2 u1 = mkc(uu.x, uu.y);
    C2 v[16];
    #pragma unroll
    for (int j = 0; j < 16; j++) { float2 t = cs[SP2(i0 + j*m)]; v[j] = mkc(t.x, t.y); }
    r16_inv(v, u1);
    #pragma unroll
    for (int j = 0; j < 16; j++) cs[SP2(i0 + j*m)] = make_float2(v[j].x, v[j].y);
    __syncthreads();
}

__device__ __forceinline__ void pass4_fwd(float2* cs) {
    #pragma unroll
    for (int w = 0; w < 4; w++) {
        const int i = 4 * (threadIdx.x + w * BT);
        int a0=SP2(i), a1=SP2(i+1), a2=SP2(i+2), a3=SP2(i+3);
        float2 fa=cs[a0], fb=cs[a1], fc=cs[a2], fd=cs[a3];
        C2 a=mkc(fa.x,fa.y), b=mkc(fb.x,fb.y), c=mkc(fc.x,fc.y), d=mkc(fd.x,fd.y);
        C2 t0=cadd(a,c), t1=csub(a,c), t2=cadd(b,d), t3=mulni(csub(b,d));
        C2 o0=cadd(t0,t2), o1=cadd(t1,t3), o2=csub(t0,t2), o3=csub(t1,t3);
        cs[a0]=make_float2(o0.x,o0.y); cs[a1]=make_float2(o1.x,o1.y);
        cs[a2]=make_float2(o2.x,o2.y); cs[a3]=make_float2(o3.x,o3.y);
    }
    __syncthreads();
}

__device__ __forceinline__ void pass4_inv(float2* cs) {
    #pragma unroll
    for (int w = 0; w < 4; w++) {
        const int i = 4 * (threadIdx.x + w * BT);
        int a0=SP2(i), a1=SP2(i+1), a2=SP2(i+2), a3=SP2(i+3);
        float2 fa=cs[a0], fb=cs[a1], fc=cs[a2], fd=cs[a3];
        C2 a=mkc(fa.x,fa.y), b=mkc(fb.x,fb.y), c=mkc(fc.x,fc.y), d=mkc(fd.x,fd.y);
        C2 p0=cadd(a,c), p1=csub(a,c), p2=cadd(b,d), p3=mulpi(csub(b,d));
        C2 o0=cadd(p0,p2), o1=cadd(p1,p3), o2=csub(p0,p2), o3=csub(p1,p3);
        cs[a0]=make_float2(o0.x,o0.y); cs[a1]=make_float2(o1.x,o1.y);
        cs[a2]=make_float2(o2.x,o2.y); cs[a3]=make_float2(o3.x,o3.y);
    }
    __syncthreads();
}

// ---- boundary passes: gmem-fused first forward / last inverse (LM=10) ------
__device__ __forceinline__ void fwd_first_strided(float2* cs, const float2* __restrict__ xr) {
    const int i0 = threadIdx.x;                  // r == i0, m = 1024
    float2 uu = g_tw[i0];
    C2 u1 = mkc(uu.x, uu.y);
    C2 v[16];
    #pragma unroll
    for (int j = 0; j < 8; j++) {
        float2 t = xr[(size_t)(i0 + j * 1024) * NPAIR];
        v[j] = mkc(t.x, t.y);
    }
    r16_fwd_zfold(v, u1);
    #pragma unroll
    for (int j = 0; j < 16; j++) cs[SP2(i0 + j*1024)] = make_float2(v[j].x, v[j].y);
    __syncthreads();
}

__device__ __forceinline__ void fwd_first_rows(float2* cs,
                                               const float* __restrict__ k0,
                                               const float* __restrict__ k1) {
    const int i0 = threadIdx.x;
    float2 uu = g_tw[i0];
    C2 u1 = mkc(uu.x, uu.y);
    C2 v[16];
    #pragma unroll
    for (int j = 0; j < 8; j++) {
        int t = i0 + j * 1024;
        v[j] = mkc(k0[t], k1[t]);
    }
    r16_fwd_zfold(v, u1);
    #pragma unroll
    for (int j = 0; j < 16; j++) cs[SP2(i0 + j*1024)] = make_float2(v[j].x, v[j].y);
    __syncthreads();
}

__device__ __forceinline__ void inv_last_strided(float2* cs, float2* __restrict__ yr) {
    const int i0 = threadIdx.x;
    float2 uu = g_tw[i0];
    C2 u1 = mkc(uu.x, uu.y);
    C2 v[16];
    #pragma unroll
    for (int j = 0; j < 16; j++) { float2 t = cs[SP2(i0 + j*1024)]; v[j] = mkc(t.x, t.y); }
    r16_inv(v, u1);
    #pragma unroll
    for (int j = 0; j < 8; j++)
        yr[(size_t)(i0 + j * 1024) * NPAIR] = make_float2(v[j].x, v[j].y);
}

// ---------------- twiddle init ----------------------------------------------
__global__ void k_twinit() {
    int j = blockIdx.x * blockDim.x + threadIdx.x;
    if (j < TW_SIZE) {
        double a = -2.0 * M_PI * (double)j / (double)FFT_N;
        g_tw[j] = make_float2((float)cos(a), (float)sin(a));
    }
}

// ------------- filter spectra -> pair-packed float4 table -------------------
__global__ void __launch_bounds__(BT, 1) k_filt(const float* __restrict__ filt) {
    extern __shared__ float2 cs[];
    const int c = blockIdx.x;
    const float* k0 = filt + (size_t)(2 * c)     * SEQ_L;
    const float* k1 = filt + (size_t)(2 * c + 1) * SEQ_L;
    fwd_first_rows(cs, k0, k1);
    pass16_fwd<6>(cs);
    pass16_fwd<2>(cs);
    pass4_fwd(cs);
    float4* out = g_kf + (size_t)c * KF_STRIDE;
    for (int f = threadIdx.x; f <= FFT_N / 2; f += BT) {
        float2 Cv = cs[SP2(drev14(f))];
        float2 Dv = cs[SP2(drev14((FFT_N - f) & (FFT_N - 1)))];
        out[f] = make_float4(Cv.x, Cv.y, Dv.x, Dv.y);
    }
}

// ------------------------------- main conv ----------------------------------
__global__ void __launch_bounds__(BT, 1) k_conv(const float2* __restrict__ x2,
                                                float2* __restrict__ y2) {
    extern __shared__ float2 cs[];
    const int b = blockIdx.x & 3;
    const int c = blockIdx.x >> 2;

    fwd_first_strided(cs, x2 + (size_t)b * SEQ_L * NPAIR + c);
    pass16_fwd<6>(cs);
    pass16_fwd<2>(cs);
    pass4_fwd(cs);

    // Pointwise multiply (conjugate-symmetry unpack/repack), coalesced kf pairs.
    const float4* __restrict__ kfp = g_kf + (size_t)c * KF_STRIDE;
    const float scale = 1.0f / (4.0f * (float)FFT_N);
    for (int f = threadIdx.x; f <= FFT_N / 2; f += BT) {
        const int p  = drev14(f);
        const int p2 = drev14((FFT_N - f) & (FFT_N - 1));
        const int sp = SP2(p), sp2 = SP2(p2);
        float2 A = cs[sp];
        float2 B = cs[sp2];
        float4 K = kfp[f];
        float ar = A.x,  ai = A.y;
        float br = B.x,  bi = -B.y;
        float cr = K.x,  ci = K.y;
        float dr = K.z,  di = -K.w;
        float apbr = ar + br, apbi = ai + bi;
        float ambr = ar - br, ambi = ai - bi;
        float cpdr = cr + dr, cpdi = ci + di;
        float cmdr = cr - dr, cmdi = ci - di;
        float Pr = apbr * cpdr - apbi * cpdi, Pi = apbr * cpdi + apbi * cpdr;
        float Qr = ambr * cmdr - ambi * cmdi, Qi = ambr * cmdi + ambi * cmdr;
        cs[sp]  = make_float2((Pr + Qi) * scale,  (Pi - Qr) * scale);
        cs[sp2] = make_float2((Pr - Qi) * scale, -(Pi + Qr) * scale);
    }
    __syncthreads();

    pass4_inv(cs);
    pass16_inv<2>(cs);
    pass16_inv<6>(cs);
    inv_last_strided(cs, y2 + (size_t)b * SEQ_L * NPAIR + c);
}

// ------------------------------ launch --------------------------------------
extern "C" void kernel_launch(void* const* d_in, const int* in_sizes, int n_in,
                              void* d_out, int out_size) {
    const float* x    = (const float*)d_in[0];
    const float* filt = (const float*)d_in[1];
    if (n_in >= 2 && in_sizes[0] == NCH * SEQ_L && in_sizes[1] == NBATCH * SEQ_L * NCH) {
        const float* t = x; x = filt; filt = t;
    }
    float* out = (float*)d_out;

    cudaFuncSetAttribute(k_filt, cudaFuncAttributeMaxDynamicSharedMemorySize, SMEM_BYTES);
    cudaFuncSetAttribute(k_conv, cudaFuncAttributeMaxDynamicSharedMemorySize, SMEM_BYTES);

    k_twinit<<<4, 256>>>();
    k_filt<<<NPAIR, BT, SMEM_BYTES>>>(filt);
    k_conv<<<NBATCH * NPAIR, BT, SMEM_BYTES>>>((const float2*)x, (float2*)out);
}

// round 4
// speedup vs baseline: 4.0625x; 1.6406x over previous
#include <cuda_runtime.h>
#include <math.h>

#define FFT_N   16384
#define SEQ_L   8192
#define NCH     1024
#define NPAIR   512
#define NBATCH  4
#define BT      1024
#define SM2 (FFT_N + (FFT_N >> 4))        // 17408 float2 (padded)
#define SMEM_BYTES (SM2 * 8)              // 139264 B

#define SP2(i) ((i) + ((i) >> 4))

// -------- device globals (no cudaMalloc allowed) ----------------------------
// Filter spectra, position-ordered: g_kf[c][2*g+h] packs spectrum positions
// {4g, 4g+1} (h=0) and {4g+2, 4g+3} (h=1) as float4 (two float2's).
__device__ float4 g_kf[(size_t)NPAIR * 8192];

// digit-reverse base-4 of a 12-bit index (6 digits). Self-inverse.
__device__ __forceinline__ int drev12(int p) {
    unsigned r = __brev((unsigned)p) >> 20;
    return (int)(((r & 0x555u) << 1) | ((r & 0xAAAu) >> 1));
}

// ----------------------------- complex helpers ------------------------------
struct C2 { float x, y; };
__device__ __forceinline__ C2 mkc(float a, float b){ C2 r; r.x=a; r.y=b; return r; }
__device__ __forceinline__ C2 cadd(C2 a, C2 b){ return mkc(a.x+b.x, a.y+b.y); }
__device__ __forceinline__ C2 csub(C2 a, C2 b){ return mkc(a.x-b.x, a.y-b.y); }
__device__ __forceinline__ C2 cmul(C2 a, C2 b){ return mkc(a.x*b.x - a.y*b.y, a.x*b.y + a.y*b.x); }
__device__ __forceinline__ C2 cmulc(C2 a, C2 b){ return mkc(a.x*b.x + a.y*b.y, a.y*b.x - a.x*b.y); } // a*conj(b)
__device__ __forceinline__ C2 mulni(C2 a){ return mkc(a.y, -a.x); }  // -i*a
__device__ __forceinline__ C2 mulpi(C2 a){ return mkc(-a.y, a.x); }  // +i*a

__device__ __forceinline__ C2 w16c(int n) {   // W_16^n (n literal -> folded)
    const float C[10] = {1.f, 0.92387953f, 0.70710678f, 0.38268343f, 0.f,
                         -0.38268343f, -0.70710678f, -0.92387953f, -1.f, -0.92387953f};
    const float S[10] = {0.f, -0.38268343f, -0.70710678f, -0.92387953f, -1.f,
                         -0.92387953f, -0.70710678f, -0.38268343f, 0.f, 0.38268343f};
    return mkc(C[n], S[n]);
}

// twiddle u1 = W_N^j = exp(-2*pi*i*j/N), j in [0,1024)
__device__ __forceinline__ C2 twiddle(int j) {
    float sv, cv;
    sincospif(-(float)j * (1.0f / 8192.0f), &sv, &cv);
    return mkc(cv, sv);
}

// ---------------- register radix-16 (two fused radix-4 layers) --------------
__device__ __forceinline__ void r16_fwd(C2* v, C2 u1) {
    C2 u2 = cmul(u1,u1);
    C2 u3 = cmul(u2,u1);
    #pragma unroll
    for (int q = 0; q < 4; q++) {
        C2 a=v[q], b=v[q+4], c=v[q+8], d=v[q+12];
        C2 t0=cadd(a,c), t1=csub(a,c), t2=cadd(b,d), t3=mulni(csub(b,d));
        v[q] = cadd(t0,t2);
        C2 o1 = cmul(cadd(t1,t3), u1);
        C2 o2 = cmul(csub(t0,t2), u2);
        C2 o3 = cmul(csub(t1,t3), u3);
        if (q) { o1=cmul(o1,w16c(q)); o2=cmul(o2,w16c(2*q)); o3=cmul(o3,w16c(3*q)); }
        v[q+4]=o1; v[q+8]=o2; v[q+12]=o3;
    }
    C2 u4 = cmul(u2,u2);
    C2 u8 = cmul(u4,u4);
    C2 u12 = cmul(u8,u4);
    #pragma unroll
    for (int s = 0; s < 4; s++) {
        C2 a=v[4*s], b=v[4*s+1], c=v[4*s+2], d=v[4*s+3];
        C2 t0=cadd(a,c), t1=csub(a,c), t2=cadd(b,d), t3=mulni(csub(b,d));
        v[4*s]   = cadd(t0,t2);
        v[4*s+1] = cmul(cadd(t1,t3), u4);
        v[4*s+2] = cmul(csub(t0,t2), u8);
        v[4*s+3] = cmul(csub(t1,t3), u12);
    }
}

// forward with v[8..15] == 0 (zero-padded input folded)
__device__ __forceinline__ void r16_fwd_zfold(C2* v, C2 u1) {
    C2 u2 = cmul(u1,u1);
    C2 u3 = cmul(u2,u1);
    #pragma unroll
    for (int q = 0; q < 4; q++) {
        C2 a=v[q], b=v[q+4];
        C2 nb = mulni(b);
        C2 o0 = cadd(a,b);
        C2 o1 = cmul(cadd(a,nb), u1);
        C2 o2 = cmul(csub(a,b), u2);
        C2 o3 = cmul(csub(a,nb), u3);
        if (q) { o1=cmul(o1,w16c(q)); o2=cmul(o2,w16c(2*q)); o3=cmul(o3,w16c(3*q)); }
        v[q]=o0; v[q+4]=o1; v[q+8]=o2; v[q+12]=o3;
    }
    C2 u4 = cmul(u2,u2);
    C2 u8 = cmul(u4,u4);
    C2 u12 = cmul(u8,u4);
    #pragma unroll
    for (int s = 0; s < 4; s++) {
        C2 a=v[4*s], b=v[4*s+1], c=v[4*s+2], d=v[4*s+3];
        C2 t0=cadd(a,c), t1=csub(a,c), t2=cadd(b,d), t3=mulni(csub(b,d));
        v[4*s]   = cadd(t0,t2);
        v[4*s+1] = cmul(cadd(t1,t3), u4);
        v[4*s+2] = cmul(csub(t0,t2), u8);
        v[4*s+3] = cmul(csub(t1,t3), u12);
    }
}

__device__ __forceinline__ void r16_inv(C2* v, C2 u1) {
    C2 u2 = cmul(u1,u1);
    C2 u4 = cmul(u2,u2);
    C2 u8 = cmul(u4,u4);
    C2 u12 = cmul(u8,u4);
    #pragma unroll
    for (int s = 0; s < 4; s++) {
        C2 a = v[4*s];
        C2 b = cmulc(v[4*s+1], u4);
        C2 c = cmulc(v[4*s+2], u8);
        C2 d = cmulc(v[4*s+3], u12);
        C2 p0=cadd(a,c), p1=csub(a,c), p2=cadd(b,d), p3=mulpi(csub(b,d));
        v[4*s]=cadd(p0,p2); v[4*s+1]=cadd(p1,p3); v[4*s+2]=csub(p0,p2); v[4*s+3]=csub(p1,p3);
    }
    C2 u3 = cmul(u2,u1);
    #pragma unroll
    for (int q = 0; q < 4; q++) {
        C2 a = v[q];
        C2 b = cmulc(v[q+4],  u1);
        C2 c = cmulc(v[q+8],  u2);
        C2 d = cmulc(v[q+12], u3);
        if (q) { b=cmulc(b,w16c(q)); c=cmulc(c,w16c(2*q)); d=cmulc(d,w16c(3*q)); }
        C2 p0=cadd(a,c), p1=csub(a,c), p2=cadd(b,d), p3=mulpi(csub(b,d));
        v[q]=cadd(p0,p2); v[q+4]=cadd(p1,p3); v[q+8]=csub(p0,p2); v[q+12]=csub(p1,p3);
    }
}

// ------------------------------ shared passes -------------------------------
template<int LM>
__device__ __forceinline__ void pass16_fwd(float2* cs) {
    const int m = 1 << LM;
    const int bf = threadIdx.x;
    const int r = bf & (m - 1);
    const int i0 = ((bf >> LM) << (LM + 4)) + r;
    C2 u1 = twiddle(r << (10 - LM));
    C2 v[16];
    #pragma unroll
    for (int j = 0; j < 16; j++) { float2 t = cs[SP2(i0 + j*m)]; v[j] = mkc(t.x, t.y); }
    r16_fwd(v, u1);
    #pragma unroll
    for (int j = 0; j < 16; j++) cs[SP2(i0 + j*m)] = make_float2(v[j].x, v[j].y);
    __syncthreads();
}

template<int LM>
__device__ __forceinline__ void pass16_inv(float2* cs) {
    const int m = 1 << LM;
    const int bf = threadIdx.x;
    const int r = bf & (m - 1);
    const int i0 = ((bf >> LM) << (LM + 4)) + r;
    C2 u1 = twiddle(r << (10 - LM));
    C2 v[16];
    #pragma unroll
    for (int j = 0; j < 16; j++) { float2 t = cs[SP2(i0 + j*m)]; v[j] = mkc(t.x, t.y); }
    r16_inv(v, u1);
    #pragma unroll
    for (int j = 0; j < 16; j++) cs[SP2(i0 + j*m)] = make_float2(v[j].x, v[j].y);
    __syncthreads();
}

// twiddle-free radix-4 butterflies (final fwd / first inv stage)
__device__ __forceinline__ void fwd4(C2& a, C2& b, C2& c, C2& d) {
    C2 t0=cadd(a,c), t1=csub(a,c), t2=cadd(b,d), t3=mulni(csub(b,d));
    a=cadd(t0,t2); b=cadd(t1,t3); c=csub(t0,t2); d=csub(t1,t3);
}
__device__ __forceinline__ void inv4(C2& a, C2& b, C2& c, C2& d) {
    C2 p0=cadd(a,c), p1=csub(a,c), p2=cadd(b,d), p3=mulpi(csub(b,d));
    a=cadd(p0,p2); b=cadd(p1,p3); c=csub(p0,p2); d=csub(p1,p3);
}

// pointwise: A=Z[f]; Braw=Z[N-f]; C=Zk[f]; Draw=Zk[N-f].
// outF <- W[f], outNF <- W[N-f]  (scaled)
__device__ __forceinline__ void pw(C2 A, C2 Braw, C2 Cv, C2 Draw, C2& outF, C2& outNF) {
    const float s = 1.0f / (4.0f * (float)FFT_N);
    float br = Braw.x, bi = -Braw.y;
    float dr = Draw.x, di = -Draw.y;
    float apbr = A.x + br, apbi = A.y + bi;
    float ambr = A.x - br, ambi = A.y - bi;
    float cpdr = Cv.x + dr, cpdi = Cv.y + di;
    float cmdr = Cv.x - dr, cmdi = Cv.y - di;
    float Pr = apbr * cpdr - apbi * cpdi, Pi = apbr * cpdi + apbi * cpdr;
    float Qr = ambr * cmdr - ambi * cmdi, Qi = ambr * cmdi + ambi * cmdr;
    outF  = mkc((Pr + Qi) * s,  (Pi - Qr) * s);
    outNF = mkc((Pr - Qi) * s, -(Pi + Qr) * s);
}

// ---- boundary passes: gmem-fused first forward / last inverse --------------
__device__ __forceinline__ void fwd_first_strided(float2* cs, const float2* __restrict__ xr) {
    const int i0 = threadIdx.x;
    C2 u1 = twiddle(i0);
    C2 v[16];
    #pragma unroll
    for (int j = 0; j < 8; j++) {
        float2 t = __ldg(&xr[(size_t)(i0 + j * 1024) * NPAIR]);
        v[j] = mkc(t.x, t.y);
    }
    r16_fwd_zfold(v, u1);
    #pragma unroll
    for (int j = 0; j < 16; j++) cs[SP2(i0 + j*1024)] = make_float2(v[j].x, v[j].y);
    __syncthreads();
}

__device__ __forceinline__ void fwd_first_rows(float2* cs,
                                               const float* __restrict__ k0,
                                               const float* __restrict__ k1) {
    const int i0 = threadIdx.x;
    C2 u1 = twiddle(i0);
    C2 v[16];
    #pragma unroll
    for (int j = 0; j < 8; j++) {
        int t = i0 + j * 1024;
        v[j] = mkc(k0[t], k1[t]);
    }
    r16_fwd_zfold(v, u1);
    #pragma unroll
    for (int j = 0; j < 16; j++) cs[SP2(i0 + j*1024)] = make_float2(v[j].x, v[j].y);
    __syncthreads();
}

__device__ __forceinline__ void inv_last_strided(float2* cs, float2* __restrict__ yr) {
    const int i0 = threadIdx.x;
    C2 u1 = twiddle(i0);
    C2 v[16];
    #pragma unroll
    for (int j = 0; j < 16; j++) { float2 t = cs[SP2(i0 + j*1024)]; v[j] = mkc(t.x, t.y); }
    r16_inv(v, u1);
    #pragma unroll
    for (int j = 0; j < 8; j++)
        yr[(size_t)(i0 + j * 1024) * NPAIR] = make_float2(v[j].x, v[j].y);
}

// ------------- filter spectra -> position-ordered table ---------------------
__global__ void __launch_bounds__(BT, 1) k_filt(const float* __restrict__ filt) {
    extern __shared__ float2 cs[];
    const int c = blockIdx.x;
    const float* k0 = filt + (size_t)(2 * c)     * SEQ_L;
    const float* k1 = filt + (size_t)(2 * c + 1) * SEQ_L;
    fwd_first_rows(cs, k0, k1);
    pass16_fwd<6>(cs);
    pass16_fwd<2>(cs);
    // final twiddle-free radix-4 stage in registers, then dense table write
    float4* out = g_kf + (size_t)c * 8192;
    for (int g = threadIdx.x; g < 4096; g += BT) {
        float2 fa = cs[SP2(4*g)],   fb = cs[SP2(4*g+1)];
        float2 fc = cs[SP2(4*g+2)], fd = cs[SP2(4*g+3)];
        C2 a=mkc(fa.x,fa.y), b=mkc(fb.x,fb.y), c2=mkc(fc.x,fc.y), d=mkc(fd.x,fd.y);
        fwd4(a, b, c2, d);
        out[2*g]   = make_float4(a.x, a.y, b.x, b.y);
        out[2*g+1] = make_float4(c2.x, c2.y, d.x, d.y);
    }
}

// ------------------------------- main conv ----------------------------------
__global__ void __launch_bounds__(BT, 1) k_conv(const float2* __restrict__ x2,
                                                float2* __restrict__ y2) {
    extern __shared__ float2 cs[];
    const int b = blockIdx.x & 3;
    const int c = blockIdx.x >> 2;

    fwd_first_strided(cs, x2 + (size_t)b * SEQ_L * NPAIR + c);
    pass16_fwd<6>(cs);
    pass16_fwd<2>(cs);

    // ---- fused: final fwd radix-4 + pointwise + first inv radix-4 ----------
    const float4* __restrict__ kt = g_kf + (size_t)c * 8192;
    for (int g = threadIdx.x; g < 4096; g += BT) {
        const int m = drev12(g);
        int g2 = 0;
        bool self = false, zero = (m == 0);
        if (!zero) {
            g2 = drev12(4096 - m);
            if (g2 < g) continue;          // pair handled by the other task
            self = (g2 == g);
        }
        // load + forward butterfly of group g
        float2 fa = cs[SP2(4*g)],   fb = cs[SP2(4*g+1)];
        float2 fc = cs[SP2(4*g+2)], fd = cs[SP2(4*g+3)];
        C2 v0=mkc(fa.x,fa.y), v1=mkc(fb.x,fb.y), v2=mkc(fc.x,fc.y), v3=mkc(fd.x,fd.y);
        fwd4(v0, v1, v2, v3);
        float4 kA0 = __ldg(&kt[2*g]), kA1 = __ldg(&kt[2*g+1]);
        C2 cA0 = mkc(kA0.x,kA0.y), cA1 = mkc(kA0.z,kA0.w);
        C2 cA2 = mkc(kA1.x,kA1.y), cA3 = mkc(kA1.z,kA1.w);

        if (zero) {
            // pairs: (f=0 self), (4096, 12288), (8192 self)
            C2 dummy;
            pw(v0, v0, cA0, cA0, v0, dummy);
            pw(v2, v2, cA2, cA2, v2, dummy);
            C2 a1 = v1, a3 = v3;
            pw(a1, a3, cA1, cA3, v1, v3);
            inv4(v0, v1, v2, v3);
            cs[SP2(4*g)]   = make_float2(v0.x,v0.y);
            cs[SP2(4*g+1)] = make_float2(v1.x,v1.y);
            cs[SP2(4*g+2)] = make_float2(v2.x,v2.y);
            cs[SP2(4*g+3)] = make_float2(v3.x,v3.y);
        } else if (self) {
            C2 a0=v0, a1=v1, a2=v2, a3=v3;
            pw(a0, a3, cA0, cA3, v0, v3);
            pw(a1, a2, cA1, cA2, v1, v2);
            inv4(v0, v1, v2, v3);
            cs[SP2(4*g)]   = make_float2(v0.x,v0.y);
            cs[SP2(4*g+1)] = make_float2(v1.x,v1.y);
            cs[SP2(4*g+2)] = make_float2(v2.x,v2.y);
            cs[SP2(4*g+3)] = make_float2(v3.x,v3.y);
        } else {
            float2 ga = cs[SP2(4*g2)],   gb = cs[SP2(4*g2+1)];
            float2 gc = cs[SP2(4*g2+2)], gd = cs[SP2(4*g2+3)];
            C2 w0=mkc(ga.x,ga.y), w1=mkc(gb.x,gb.y), w2=mkc(gc.x,gc.y), w3=mkc(gd.x,gd.y);
            fwd4(w0, w1, w2, w3);
            float4 kB0 = __ldg(&kt[2*g2]), kB1 = __ldg(&kt[2*g2+1]);
            C2 cB0 = mkc(kB0.x,kB0.y), cB1 = mkc(kB0.z,kB0.w);
            C2 cB2 = mkc(kB1.x,kB1.y), cB3 = mkc(kB1.z,kB1.w);
            pw(v0, w3, cA0, cB3, v0, w3);
            pw(v1, w2, cA1, cB2, v1, w2);
            pw(v2, w1, cA2, cB1, v2, w1);
            pw(v3, w0, cA3, cB0, v3, w0);
            inv4(v0, v1, v2, v3);
            inv4(w0, w1, w2, w3);
            cs[SP2(4*g)]    = make_float2(v0.x,v0.y);
            cs[SP2(4*g+1)]  = make_float2(v1.x,v1.y);
            cs[SP2(4*g+2)]  = make_float2(v2.x,v2.y);
            cs[SP2(4*g+3)]  = make_float2(v3.x,v3.y);
            cs[SP2(4*g2)]   = make_float2(w0.x,w0.y);
            cs[SP2(4*g2+1)] = make_float2(w1.x,w1.y);
            cs[SP2(4*g2+2)] = make_float2(w2.x,w2.y);
            cs[SP2(4*g2+3)] = make_float2(w3.x,w3.y);
        }
    }
    __syncthreads();

    pass16_inv<2>(cs);
    pass16_inv<6>(cs);
    inv_last_strided(cs, y2 + (size_t)b * SEQ_L * NPAIR + c);
}

// ------------------------------ launch --------------------------------------
extern "C" void kernel_launch(void* const* d_in, const int* in_sizes, int n_in,
                              void* d_out, int out_size) {
    const float* x    = (const float*)d_in[0];
    const float* filt = (const float*)d_in[1];
    if (n_in >= 2 && in_sizes[0] == NCH * SEQ_L && in_sizes[1] == NBATCH * SEQ_L * NCH) {
        const float* t = x; x = filt; filt = t;
    }
    float* out = (float*)d_out;

    cudaFuncSetAttribute(k_filt, cudaFuncAttributeMaxDynamicSharedMemorySize, SMEM_BYTES);
    cudaFuncSetAttribute(k_conv, cudaFuncAttributeMaxDynamicSharedMemorySize, SMEM_BYTES);

    k_filt<<<NPAIR, BT, SMEM_BYTES>>>(filt);
    k_conv<<<NBATCH * NPAIR, BT, SMEM_BYTES>>>((const float2*)x, (float2*)out);
}

// round 5
// speedup vs baseline: 4.0966x; 1.0084x over previous
#include <cuda_runtime.h>
#include <math.h>

#define FFT_N   16384
#define SEQ_L   8192
#define NCH     1024
#define NPAIR   512
#define NBATCH  4
#define BT      1024
#define SM2 (FFT_N + (FFT_N >> 4))        // 17408 float2 (padded)
#define SMEM_BYTES (SM2 * 8)              // 139264 B

#define SP2(i) ((i) + ((i) >> 4))

// -------- device globals (no cudaMalloc allowed) ----------------------------
// Filter spectra, position-ordered: g_kf[c][2*g+h] packs spectrum positions
// {4g, 4g+1} (h=0) and {4g+2, 4g+3} (h=1) as float4 (two float2's).
__device__ float4 g_kf[(size_t)NPAIR * 8192];

// digit-reverse base-4 of a 12-bit index (6 digits). Self-inverse.
__device__ __forceinline__ int drev12(int p) {
    unsigned r = __brev((unsigned)p) >> 20;
    return (int)(((r & 0x555u) << 1) | ((r & 0xAAAu) >> 1));
}

// ----------------------------- complex helpers ------------------------------
struct C2 { float x, y; };
__device__ __forceinline__ C2 mkc(float a, float b){ C2 r; r.x=a; r.y=b; return r; }
__device__ __forceinline__ C2 cadd(C2 a, C2 b){ return mkc(a.x+b.x, a.y+b.y); }
__device__ __forceinline__ C2 csub(C2 a, C2 b){ return mkc(a.x-b.x, a.y-b.y); }
__device__ __forceinline__ C2 cmul(C2 a, C2 b){ return mkc(a.x*b.x - a.y*b.y, a.x*b.y + a.y*b.x); }
__device__ __forceinline__ C2 cmulc(C2 a, C2 b){ return mkc(a.x*b.x + a.y*b.y, a.y*b.x - a.x*b.y); } // a*conj(b)
__device__ __forceinline__ C2 mulni(C2 a){ return mkc(a.y, -a.x); }  // -i*a
__device__ __forceinline__ C2 mulpi(C2 a){ return mkc(-a.y, a.x); }  // +i*a

__device__ __forceinline__ C2 w16c(int n) {   // W_16^n (n literal -> folded)
    const float C[10] = {1.f, 0.92387953f, 0.70710678f, 0.38268343f, 0.f,
                         -0.38268343f, -0.70710678f, -0.92387953f, -1.f, -0.92387953f};
    const float S[10] = {0.f, -0.38268343f, -0.70710678f, -0.92387953f, -1.f,
                         -0.92387953f, -0.70710678f, -0.38268343f, 0.f, 0.38268343f};
    return mkc(C[n], S[n]);
}

// twiddle u1 = W_N^j = exp(-2*pi*i*j/N), j in [0,1024)
__device__ __forceinline__ C2 twiddle(int j) {
    float sv, cv;
    sincospif(-(float)j * (1.0f / 8192.0f), &sv, &cv);
    return mkc(cv, sv);
}

// ---------------- register radix-16 (two fused radix-4 layers) --------------
__device__ __forceinline__ void r16_fwd(C2* v, C2 u1) {
    C2 u2 = cmul(u1,u1);
    C2 u3 = cmul(u2,u1);
    #pragma unroll
    for (int q = 0; q < 4; q++) {
        C2 a=v[q], b=v[q+4], c=v[q+8], d=v[q+12];
        C2 t0=cadd(a,c), t1=csub(a,c), t2=cadd(b,d), t3=mulni(csub(b,d));
        v[q] = cadd(t0,t2);
        C2 o1 = cmul(cadd(t1,t3), u1);
        C2 o2 = cmul(csub(t0,t2), u2);
        C2 o3 = cmul(csub(t1,t3), u3);
        if (q) { o1=cmul(o1,w16c(q)); o2=cmul(o2,w16c(2*q)); o3=cmul(o3,w16c(3*q)); }
        v[q+4]=o1; v[q+8]=o2; v[q+12]=o3;
    }
    C2 u4 = cmul(u2,u2);
    C2 u8 = cmul(u4,u4);
    C2 u12 = cmul(u8,u4);
    #pragma unroll
    for (int s = 0; s < 4; s++) {
        C2 a=v[4*s], b=v[4*s+1], c=v[4*s+2], d=v[4*s+3];
        C2 t0=cadd(a,c), t1=csub(a,c), t2=cadd(b,d), t3=mulni(csub(b,d));
        v[4*s]   = cadd(t0,t2);
        v[4*s+1] = cmul(cadd(t1,t3), u4);
        v[4*s+2] = cmul(csub(t0,t2), u8);
        v[4*s+3] = cmul(csub(t1,t3), u12);
    }
}

// forward with v[8..15] == 0 (zero-padded input folded)
__device__ __forceinline__ void r16_fwd_zfold(C2* v, C2 u1) {
    C2 u2 = cmul(u1,u1);
    C2 u3 = cmul(u2,u1);
    #pragma unroll
    for (int q = 0; q < 4; q++) {
        C2 a=v[q], b=v[q+4];
        C2 nb = mulni(b);
        C2 o0 = cadd(a,b);
        C2 o1 = cmul(cadd(a,nb), u1);
        C2 o2 = cmul(csub(a,b), u2);
        C2 o3 = cmul(csub(a,nb), u3);
        if (q) { o1=cmul(o1,w16c(q)); o2=cmul(o2,w16c(2*q)); o3=cmul(o3,w16c(3*q)); }
        v[q]=o0; v[q+4]=o1; v[q+8]=o2; v[q+12]=o3;
    }
    C2 u4 = cmul(u2,u2);
    C2 u8 = cmul(u4,u4);
    C2 u12 = cmul(u8,u4);
    #pragma unroll
    for (int s = 0; s < 4; s++) {
        C2 a=v[4*s], b=v[4*s+1], c=v[4*s+2], d=v[4*s+3];
        C2 t0=cadd(a,c), t1=csub(a,c), t2=cadd(b,d), t3=mulni(csub(b,d));
        v[4*s]   = cadd(t0,t2);
        v[4*s+1] = cmul(cadd(t1,t3), u4);
        v[4*s+2] = cmul(csub(t0,t2), u8);
        v[4*s+3] = cmul(csub(t1,t3), u12);
    }
}

__device__ __forceinline__ void r16_inv(C2* v, C2 u1) {
    C2 u2 = cmul(u1,u1);
    C2 u4 = cmul(u2,u2);
    C2 u8 = cmul(u4,u4);
    C2 u12 = cmul(u8,u4);
    #pragma unroll
    for (int s = 0; s < 4; s++) {
        C2 a = v[4*s];
        C2 b = cmulc(v[4*s+1], u4);
        C2 c = cmulc(v[4*s+2], u8);
        C2 d = cmulc(v[4*s+3], u12);
        C2 p0=cadd(a,c), p1=csub(a,c), p2=cadd(b,d), p3=mulpi(csub(b,d));
        v[4*s]=cadd(p0,p2); v[4*s+1]=cadd(p1,p3); v[4*s+2]=csub(p0,p2); v[4*s+3]=csub(p1,p3);
    }
    C2 u3 = cmul(u2,u1);
    #pragma unroll
    for (int q = 0; q < 4; q++) {
        C2 a = v[q];
        C2 b = cmulc(v[q+4],  u1);
        C2 c = cmulc(v[q+8],  u2);
        C2 d = cmulc(v[q+12], u3);
        if (q) { b=cmulc(b,w16c(q)); c=cmulc(c,w16c(2*q)); d=cmulc(d,w16c(3*q)); }
        C2 p0=cadd(a,c), p1=csub(a,c), p2=cadd(b,d), p3=mulpi(csub(b,d));
        v[q]=cadd(p0,p2); v[q+4]=cadd(p1,p3); v[q+8]=csub(p0,p2); v[q+12]=csub(p1,p3);
    }
}

// ------------------------------ shared passes -------------------------------
template<int LM>
__device__ __forceinline__ void pass16_fwd(float2* cs) {
    const int m = 1 << LM;
    const int bf = threadIdx.x;
    const int r = bf & (m - 1);
    const int i0 = ((bf >> LM) << (LM + 4)) + r;
    C2 u1 = twiddle(r << (10 - LM));
    C2 v[16];
    #pragma unroll
    for (int j = 0; j < 16; j++) { float2 t = cs[SP2(i0 + j*m)]; v[j] = mkc(t.x, t.y); }
    r16_fwd(v, u1);
    #pragma unroll
    for (int j = 0; j < 16; j++) cs[SP2(i0 + j*m)] = make_float2(v[j].x, v[j].y);
    __syncthreads();
}

template<int LM>
__device__ __forceinline__ void pass16_inv(float2* cs) {
    const int m = 1 << LM;
    const int bf = threadIdx.x;
    const int r = bf & (m - 1);
    const int i0 = ((bf >> LM) << (LM + 4)) + r;
    C2 u1 = twiddle(r << (10 - LM));
    C2 v[16];
    #pragma unroll
    for (int j = 0; j < 16; j++) { float2 t = cs[SP2(i0 + j*m)]; v[j] = mkc(t.x, t.y); }
    r16_inv(v, u1);
    #pragma unroll
    for (int j = 0; j < 16; j++) cs[SP2(i0 + j*m)] = make_float2(v[j].x, v[j].y);
    __syncthreads();
}

// twiddle-free radix-4 butterflies (final fwd / first inv stage)
__device__ __forceinline__ void fwd4(C2& a, C2& b, C2& c, C2& d) {
    C2 t0=cadd(a,c), t1=csub(a,c), t2=cadd(b,d), t3=mulni(csub(b,d));
    a=cadd(t0,t2); b=cadd(t1,t3); c=csub(t0,t2); d=csub(t1,t3);
}
__device__ __forceinline__ void inv4(C2& a, C2& b, C2& c, C2& d) {
    C2 p0=cadd(a,c), p1=csub(a,c), p2=cadd(b,d), p3=mulpi(csub(b,d));
    a=cadd(p0,p2); b=cadd(p1,p3); c=csub(p0,p2); d=csub(p1,p3);
}

// pointwise: A=Z[f]; Braw=Z[N-f]; C=Zk[f]; Draw=Zk[N-f].
// outF <- W[f], outNF <- W[N-f]  (scaled)
__device__ __forceinline__ void pw(C2 A, C2 Braw, C2 Cv, C2 Draw, C2& outF, C2& outNF) {
    const float s = 1.0f / (4.0f * (float)FFT_N);
    float br = Braw.x, bi = -Braw.y;
    float dr = Draw.x, di = -Draw.y;
    float apbr = A.x + br, apbi = A.y + bi;
    float ambr = A.x - br, ambi = A.y - bi;
    float cpdr = Cv.x + dr, cpdi = Cv.y + di;
    float cmdr = Cv.x - dr, cmdi = Cv.y - di;
    float Pr = apbr * cpdr - apbi * cpdi, Pi = apbr * cpdi + apbi * cpdr;
    float Qr = ambr * cmdr - ambi * cmdi, Qi = ambr * cmdi + ambi * cmdr;
    outF  = mkc((Pr + Qi) * s,  (Pi - Qr) * s);
    outNF = mkc((Pr - Qi) * s, -(Pi + Qr) * s);
}

// ---- boundary passes: gmem-fused first forward / last inverse --------------
__device__ __forceinline__ void fwd_first_strided(float2* cs, const float2* __restrict__ xr) {
    const int i0 = threadIdx.x;
    C2 u1 = twiddle(i0);
    C2 v[16];
    #pragma unroll
    for (int j = 0; j < 8; j++) {
        float2 t = __ldg(&xr[(size_t)(i0 + j * 1024) * NPAIR]);
        v[j] = mkc(t.x, t.y);
    }
    r16_fwd_zfold(v, u1);
    #pragma unroll
    for (int j = 0; j < 16; j++) cs[SP2(i0 + j*1024)] = make_float2(v[j].x, v[j].y);
    __syncthreads();
}

__device__ __forceinline__ void fwd_first_rows(float2* cs,
                                               const float* __restrict__ k0,
                                               const float* __restrict__ k1) {
    const int i0 = threadIdx.x;
    C2 u1 = twiddle(i0);
    C2 v[16];
    #pragma unroll
    for (int j = 0; j < 8; j++) {
        int t = i0 + j * 1024;
        v[j] = mkc(k0[t], k1[t]);
    }
    r16_fwd_zfold(v, u1);
    #pragma unroll
    for (int j = 0; j < 16; j++) cs[SP2(i0 + j*1024)] = make_float2(v[j].x, v[j].y);
    __syncthreads();
}

__device__ __forceinline__ void inv_last_strided(float2* cs, float2* __restrict__ yr) {
    const int i0 = threadIdx.x;
    C2 u1 = twiddle(i0);
    C2 v[16];
    #pragma unroll
    for (int j = 0; j < 16; j++) { float2 t = cs[SP2(i0 + j*1024)]; v[j] = mkc(t.x, t.y); }
    r16_inv(v, u1);
    #pragma unroll
    for (int j = 0; j < 8; j++)
        yr[(size_t)(i0 + j * 1024) * NPAIR] = make_float2(v[j].x, v[j].y);
}

// ------------- filter spectra -> position-ordered table ---------------------
__global__ void __launch_bounds__(BT, 1) k_filt(const float* __restrict__ filt) {
    extern __shared__ float2 cs[];
    const int c = blockIdx.x;
    const float* k0 = filt + (size_t)(2 * c)     * SEQ_L;
    const float* k1 = filt + (size_t)(2 * c + 1) * SEQ_L;
    fwd_first_rows(cs, k0, k1);
    pass16_fwd<6>(cs);
    pass16_fwd<2>(cs);
    // final twiddle-free radix-4 stage in registers, then dense table write
    float4* out = g_kf + (size_t)c * 8192;
    for (int g = threadIdx.x; g < 4096; g += BT) {
        float2 fa = cs[SP2(4*g)],   fb = cs[SP2(4*g+1)];
        float2 fc = cs[SP2(4*g+2)], fd = cs[SP2(4*g+3)];
        C2 a=mkc(fa.x,fa.y), b=mkc(fb.x,fb.y), c2=mkc(fc.x,fc.y), d=mkc(fd.x,fd.y);
        fwd4(a, b, c2, d);
        out[2*g]   = make_float4(a.x, a.y, b.x, b.y);
        out[2*g+1] = make_float4(c2.x, c2.y, d.x, d.y);
    }
}

// ------------------------------- main conv ----------------------------------
__global__ void __launch_bounds__(BT, 1) k_conv(const float2* __restrict__ x2,
                                                float2* __restrict__ y2) {
    extern __shared__ float2 cs[];
    const int b = blockIdx.x & 3;
    const int c = blockIdx.x >> 2;

    fwd_first_strided(cs, x2 + (size_t)b * SEQ_L * NPAIR + c);
    pass16_fwd<6>(cs);
    pass16_fwd<2>(cs);

    // ---- fused: final fwd radix-4 + pointwise + first inv radix-4 ----------
    const float4* __restrict__ kt = g_kf + (size_t)c * 8192;
    for (int g = threadIdx.x; g < 4096; g += BT) {
        const int m = drev12(g);
        int g2 = 0;
        bool self = false, zero = (m == 0);
        if (!zero) {
            g2 = drev12(4096 - m);
            if (g2 < g) continue;          // pair handled by the other task
            self = (g2 == g);
        }
        // load + forward butterfly of group g
        float2 fa = cs[SP2(4*g)],   fb = cs[SP2(4*g+1)];
        float2 fc = cs[SP2(4*g+2)], fd = cs[SP2(4*g+3)];
        C2 v0=mkc(fa.x,fa.y), v1=mkc(fb.x,fb.y), v2=mkc(fc.x,fc.y), v3=mkc(fd.x,fd.y);
        fwd4(v0, v1, v2, v3);
        float4 kA0 = __ldg(&kt[2*g]), kA1 = __ldg(&kt[2*g+1]);
        C2 cA0 = mkc(kA0.x,kA0.y), cA1 = mkc(kA0.z,kA0.w);
        C2 cA2 = mkc(kA1.x,kA1.y), cA3 = mkc(kA1.z,kA1.w);

        if (zero) {
            // pairs: (f=0 self), (4096, 12288), (8192 self)
            C2 dummy;
            pw(v0, v0, cA0, cA0, v0, dummy);
            pw(v2, v2, cA2, cA2, v2, dummy);
            C2 a1 = v1, a3 = v3;
            pw(a1, a3, cA1, cA3, v1, v3);
            inv4(v0, v1, v2, v3);
            cs[SP2(4*g)]   = make_float2(v0.x,v0.y);
            cs[SP2(4*g+1)] = make_float2(v1.x,v1.y);
            cs[SP2(4*g+2)] = make_float2(v2.x,v2.y);
            cs[SP2(4*g+3)] = make_float2(v3.x,v3.y);
        } else if (self) {
            C2 a0=v0, a1=v1, a2=v2, a3=v3;
            pw(a0, a3, cA0, cA3, v0, v3);
            pw(a1, a2, cA1, cA2, v1, v2);
            inv4(v0, v1, v2, v3);
            cs[SP2(4*g)]   = make_float2(v0.x,v0.y);
            cs[SP2(4*g+1)] = make_float2(v1.x,v1.y);
            cs[SP2(4*g+2)] = make_float2(v2.x,v2.y);
            cs[SP2(4*g+3)] = make_float2(v3.x,v3.y);
        } else {
            float2 ga = cs[SP2(4*g2)],   gb = cs[SP2(4*g2+1)];
            float2 gc = cs[SP2(4*g2+2)], gd = cs[SP2(4*g2+3)];
            C2 w0=mkc(ga.x,ga.y), w1=mkc(gb.x,gb.y), w2=mkc(gc.x,gc.y), w3=mkc(gd.x,gd.y);
            fwd4(w0, w1, w2, w3);
            float4 kB0 = __ldg(&kt[2*g2]), kB1 = __ldg(&kt[2*g2+1]);
            C2 cB0 = mkc(kB0.x,kB0.y), cB1 = mkc(kB0.z,kB0.w);
            C2 cB2 = mkc(kB1.x,kB1.y), cB3 = mkc(kB1.z,kB1.w);
            pw(v0, w3, cA0, cB3, v0, w3);
            pw(v1, w2, cA1, cB2, v1, w2);
            pw(v2, w1, cA2, cB1, v2, w1);
            pw(v3, w0, cA3, cB0, v3, w0);
            inv4(v0, v1, v2, v3);
            inv4(w0, w1, w2, w3);
            cs[SP2(4*g)]    = make_float2(v0.x,v0.y);
            cs[SP2(4*g+1)]  = make_float2(v1.x,v1.y);
            cs[SP2(4*g+2)]  = make_float2(v2.x,v2.y);
            cs[SP2(4*g+3)]  = make_float2(v3.x,v3.y);
            cs[SP2(4*g2)]   = make_float2(w0.x,w0.y);
            cs[SP2(4*g2+1)] = make_float2(w1.x,w1.y);
            cs[SP2(4*g2+2)] = make_float2(w2.x,w2.y);
            cs[SP2(4*g2+3)] = make_float2(w3.x,w3.y);
        }
    }
    __syncthreads();

    pass16_inv<2>(cs);
    pass16_inv<6>(cs);
    inv_last_strided(cs, y2 + (size_t)b * SEQ_L * NPAIR + c);
}

// ------------------------------ launch --------------------------------------
extern "C" void kernel_launch(void* const* d_in, const int* in_sizes, int n_in,
                              void* d_out, int out_size) {
    const float* x    = (const float*)d_in[0];
    const float* filt = (const float*)d_in[1];
    if (n_in >= 2 && in_sizes[0] == NCH * SEQ_L && in_sizes[1] == NBATCH * SEQ_L * NCH) {
        const float* t = x; x = filt; filt = t;
    }
    float* out = (float*)d_out;

    cudaFuncSetAttribute(k_filt, cudaFuncAttributeMaxDynamicSharedMemorySize, SMEM_BYTES);
    cudaFuncSetAttribute(k_conv, cudaFuncAttributeMaxDynamicSharedMemorySize, SMEM_BYTES);

    k_filt<<<NPAIR, BT, SMEM_BYTES>>>(filt);
    k_conv<<<NBATCH * NPAIR, BT, SMEM_BYTES>>>((const float2*)x, (float2*)out);
}

// round 7
// speedup vs baseline: 4.3257x; 1.0559x over previous
#include <cuda_runtime.h>
#include <math.h>

#define SEQ_L  8192
#define NPAIR  512
#define NBATCH 4
#define FFT_N  16384
#define ROWLEN 1088                 // 1024 + pad
#define SP2(i) ((i) + ((i) >> 4))

// -------- device globals (no cudaMalloc allowed) ----------------------------
__device__ float2 g_B[(size_t)NBATCH * NPAIR * 16 * 1024];    // 268 MB staging
__device__ float2 g_kf[(size_t)NPAIR * 16 * 1024];            // 67 MB filter table
__constant__ int c_jA[8] = {0, 1, 4, 5, 6, 7, 8, 9};
__constant__ int c_jB[8] = {2, 3, 15, 14, 13, 12, 11, 10};

// ----------------------------- complex helpers ------------------------------
struct C2 { float x, y; };
__device__ __forceinline__ C2 mkc(float a, float b){ C2 r; r.x=a; r.y=b; return r; }
__device__ __forceinline__ C2 cadd(C2 a, C2 b){ return mkc(a.x+b.x, a.y+b.y); }
__device__ __forceinline__ C2 csub(C2 a, C2 b){ return mkc(a.x-b.x, a.y-b.y); }
__device__ __forceinline__ C2 cmul(C2 a, C2 b){ return mkc(a.x*b.x - a.y*b.y, a.x*b.y + a.y*b.x); }
__device__ __forceinline__ C2 cmulc(C2 a, C2 b){ return mkc(a.x*b.x + a.y*b.y, a.y*b.x - a.x*b.y); }
__device__ __forceinline__ C2 mulni(C2 a){ return mkc(a.y, -a.x); }
__device__ __forceinline__ C2 mulpi(C2 a){ return mkc(-a.y, a.x); }

__device__ __forceinline__ C2 w16c(int n) {
    const float C[10] = {1.f, 0.92387953f, 0.70710678f, 0.38268343f, 0.f,
                         -0.38268343f, -0.70710678f, -0.92387953f, -1.f, -0.92387953f};
    const float S[10] = {0.f, -0.38268343f, -0.70710678f, -0.92387953f, -1.f,
                         -0.92387953f, -0.70710678f, -0.38268343f, 0.f, 0.38268343f};
    return mkc(C[n], S[n]);
}
__device__ __forceinline__ C2 twN(int j) {   // W_16384^j
    float sv, cv; sincospif(-(float)j * (1.0f/8192.0f), &sv, &cv); return mkc(cv, sv);
}
__device__ __forceinline__ C2 tw1k(int j) {  // W_1024^j
    float sv, cv; sincospif(-(float)j * (1.0f/512.0f), &sv, &cv); return mkc(cv, sv);
}
// digit-reverse base-4 of 10-bit index (5 digits). Self-inverse.
__device__ __forceinline__ int drev10(int p) {
    unsigned r = __brev((unsigned)p) >> 22;
    return (int)(((r & 0x155u) << 1) | ((r & 0x2AAu) >> 1));
}

// ---------------- register radix-16 (two fused radix-4 layers) --------------
__device__ __forceinline__ void r16_fwd(C2* v, C2 u1) {
    C2 u2 = cmul(u1,u1);
    C2 u3 = cmul(u2,u1);
    #pragma unroll
    for (int q = 0; q < 4; q++) {
        C2 a=v[q], b=v[q+4], c=v[q+8], d=v[q+12];
        C2 t0=cadd(a,c), t1=csub(a,c), t2=cadd(b,d), t3=mulni(csub(b,d));
        v[q] = cadd(t0,t2);
        C2 o1 = cmul(cadd(t1,t3), u1);
        C2 o2 = cmul(csub(t0,t2), u2);
        C2 o3 = cmul(csub(t1,t3), u3);
        if (q) { o1=cmul(o1,w16c(q)); o2=cmul(o2,w16c(2*q)); o3=cmul(o3,w16c(3*q)); }
        v[q+4]=o1; v[q+8]=o2; v[q+12]=o3;
    }
    C2 u4 = cmul(u2,u2);
    C2 u8 = cmul(u4,u4);
    C2 u12 = cmul(u8,u4);
    #pragma unroll
    for (int s = 0; s < 4; s++) {
        C2 a=v[4*s], b=v[4*s+1], c=v[4*s+2], d=v[4*s+3];
        C2 t0=cadd(a,c), t1=csub(a,c), t2=cadd(b,d), t3=mulni(csub(b,d));
        v[4*s]   = cadd(t0,t2);
        v[4*s+1] = cmul(cadd(t1,t3), u4);
        v[4*s+2] = cmul(csub(t0,t2), u8);
        v[4*s+3] = cmul(csub(t1,t3), u12);
    }
}

__device__ __forceinline__ void r16_fwd_zfold(C2* v, C2 u1) {
    C2 u2 = cmul(u1,u1);
    C2 u3 = cmul(u2,u1);
    #pragma unroll
    for (int q = 0; q < 4; q++) {
        C2 a=v[q], b=v[q+4];
        C2 nb = mulni(b);
        C2 o0 = cadd(a,b);
        C2 o1 = cmul(cadd(a,nb), u1);
        C2 o2 = cmul(csub(a,b), u2);
        C2 o3 = cmul(csub(a,nb), u3);
        if (q) { o1=cmul(o1,w16c(q)); o2=cmul(o2,w16c(2*q)); o3=cmul(o3,w16c(3*q)); }
        v[q]=o0; v[q+4]=o1; v[q+8]=o2; v[q+12]=o3;
    }
    C2 u4 = cmul(u2,u2);
    C2 u8 = cmul(u4,u4);
    C2 u12 = cmul(u8,u4);
    #pragma unroll
    for (int s = 0; s < 4; s++) {
        C2 a=v[4*s], b=v[4*s+1], c=v[4*s+2], d=v[4*s+3];
        C2 t0=cadd(a,c), t1=csub(a,c), t2=cadd(b,d), t3=mulni(csub(b,d));
        v[4*s]   = cadd(t0,t2);
        v[4*s+1] = cmul(cadd(t1,t3), u4);
        v[4*s+2] = cmul(csub(t0,t2), u8);
        v[4*s+3] = cmul(csub(t1,t3), u12);
    }
}

__device__ __forceinline__ void r16_inv(C2* v, C2 u1) {
    C2 u2 = cmul(u1,u1);
    C2 u4 = cmul(u2,u2);
    C2 u8 = cmul(u4,u4);
    C2 u12 = cmul(u8,u4);
    #pragma unroll
    for (int s = 0; s < 4; s++) {
        C2 a = v[4*s];
        C2 b = cmulc(v[4*s+1], u4);
        C2 c = cmulc(v[4*s+2], u8);
        C2 d = cmulc(v[4*s+3], u12);
        C2 p0=cadd(a,c), p1=csub(a,c), p2=cadd(b,d), p3=mulpi(csub(b,d));
        v[4*s]=cadd(p0,p2); v[4*s+1]=cadd(p1,p3); v[4*s+2]=csub(p0,p2); v[4*s+3]=csub(p1,p3);
    }
    C2 u3 = cmul(u2,u1);
    #pragma unroll
    for (int q = 0; q < 4; q++) {
        C2 a = v[q];
        C2 b = cmulc(v[q+4],  u1);
        C2 c = cmulc(v[q+8],  u2);
        C2 d = cmulc(v[q+12], u3);
        if (q) { b=cmulc(b,w16c(q)); c=cmulc(c,w16c(2*q)); d=cmulc(d,w16c(3*q)); }
        C2 p0=cadd(a,c), p1=csub(a,c), p2=cadd(b,d), p3=mulpi(csub(b,d));
        v[q]=cadd(p0,p2); v[q+4]=cadd(p1,p3); v[q+8]=csub(p0,p2); v[q+12]=csub(p1,p3);
    }
}

__device__ __forceinline__ void fwd4(C2& a, C2& b, C2& c, C2& d) {
    C2 t0=cadd(a,c), t1=csub(a,c), t2=cadd(b,d), t3=mulni(csub(b,d));
    a=cadd(t0,t2); b=cadd(t1,t3); c=csub(t0,t2); d=csub(t1,t3);
}
__device__ __forceinline__ void inv4(C2& a, C2& b, C2& c, C2& d) {
    C2 p0=cadd(a,c), p1=csub(a,c), p2=cadd(b,d), p3=mulpi(csub(b,d));
    a=cadd(p0,p2); b=cadd(p1,p3); c=csub(p0,p2); d=csub(p1,p3);
}

// pointwise packed-real product: A=Z[f], Braw=Z[N-f], Cv=Zk[f], Draw=Zk[N-f]
__device__ __forceinline__ void pw(C2 A, C2 Braw, C2 Cv, C2 Draw, C2& outF, C2& outNF) {
    const float s = 1.0f / (4.0f * (float)FFT_N);
    float br = Braw.x, bi = -Braw.y;
    float dr = Draw.x, di = -Draw.y;
    float apbr = A.x + br, apbi = A.y + bi;
    float ambr = A.x - br, ambi = A.y - bi;
    float cpdr = Cv.x + dr, cpdi = Cv.y + di;
    float cmdr = Cv.x - dr, cmdi = Cv.y - di;
    float Pr = apbr * cpdr - apbi * cpdi, Pi = apbr * cpdi + apbi * cpdr;
    float Qr = ambr * cmdr - ambi * cmdi, Qi = ambr * cmdi + ambi * cmdr;
    outF  = mkc((Pr + Qi) * s,  (Pi - Qr) * s);
    outNF = mkc((Pr - Qi) * s, -(Pi + Qr) * s);
}

// --------------------- 1024-point row passes in smem ------------------------
__device__ __forceinline__ C2 lds(const float2* s, int i){ float2 t = s[SP2(i)]; return mkc(t.x,t.y); }
__device__ __forceinline__ void sts(float2* s, int i, C2 v){ s[SP2(i)] = make_float2(v.x,v.y); }

__device__ __forceinline__ void row_fwd(float2* s, int bf, int LM) {
    const int m = 1 << LM;
    const int r = bf & (m - 1);
    const int i0 = ((bf >> LM) << (LM + 4)) + r;
    C2 u1 = tw1k(r << (6 - LM));
    C2 v[16];
    #pragma unroll
    for (int j = 0; j < 16; j++) v[j] = lds(s, i0 + j*m);
    r16_fwd(v, u1);
    #pragma unroll
    for (int j = 0; j < 16; j++) sts(s, i0 + j*m, v[j]);
}
__device__ __forceinline__ void row_inv(float2* s, int bf, int LM) {
    const int m = 1 << LM;
    const int r = bf & (m - 1);
    const int i0 = ((bf >> LM) << (LM + 4)) + r;
    C2 u1 = tw1k(r << (6 - LM));
    C2 v[16];
    #pragma unroll
    for (int j = 0; j < 16; j++) v[j] = lds(s, i0 + j*m);
    r16_inv(v, u1);
    #pragma unroll
    for (int j = 0; j < 16; j++) sts(s, i0 + j*m, v[j]);
}

// ---------------- kA: x -> first 16-pt stage -> g_B (transposed) ------------
__global__ void __launch_bounds__(1024) kA(const float2* __restrict__ x2) {
    __shared__ float2 tile[32][33];
    const int tx = threadIdx.x & 31, ty = threadIdx.x >> 5;
    const int b = blockIdx.z;
    const int pr0 = blockIdx.x * 32, n20 = blockIdx.y * 32;
    const float2* xb = x2 + (size_t)b * SEQ_L * NPAIR;
    const int n2 = n20 + ty;
    C2 v[16];
    #pragma unroll
    for (int j = 0; j < 8; j++) {
        float2 t = __ldg(&xb[(size_t)(j * 1024 + n2) * NPAIR + pr0 + tx]);
        v[j] = mkc(t.x, t.y);
    }
    r16_fwd_zfold(v, twN(n2));
    #pragma unroll
    for (int j = 0; j < 16; j++) {
        __syncthreads();
        tile[ty][tx] = make_float2(v[j].x, v[j].y);
        __syncthreads();
        g_B[((size_t)(b * NPAIR + pr0 + ty) * 16 + j) * 1024 + n20 + tx] = tile[tx][ty];
    }
}

// ---------------- kAf: filt -> first stage -> g_kf (coalesced) --------------
__global__ void __launch_bounds__(1024) kAf(const float* __restrict__ filt) {
    const int n2 = threadIdx.x, pr = blockIdx.x;
    const float* k0 = filt + (size_t)(2 * pr) * SEQ_L;
    const float* k1 = k0 + SEQ_L;
    C2 v[16];
    #pragma unroll
    for (int j = 0; j < 8; j++) {
        int t = j * 1024 + n2;
        v[j] = mkc(k0[t], k1[t]);
    }
    r16_fwd_zfold(v, twN(n2));
    #pragma unroll
    for (int j = 0; j < 16; j++)
        g_kf[((size_t)pr * 16 + j) * 1024 + n2] = make_float2(v[j].x, v[j].y);
}

// ---------------- kBf: forward 1024-FFT of filter rows (in place) -----------
__global__ void __launch_bounds__(128) kBf() {
    __shared__ float2 s0[ROWLEN], s1[ROWLEN];
    const int t = threadIdx.x;
    const int pr = blockIdx.y, j0 = blockIdx.x * 2;
    float2* r0 = g_kf + ((size_t)pr * 16 + j0) * 1024;
    float2* r1 = r0 + 1024;
    for (int i = t; i < 1024; i += 128) { s0[SP2(i)] = r0[i]; s1[SP2(i)] = r1[i]; }
    __syncthreads();
    float2* srow = (t >= 64) ? s1 : s0;
    const int bf = t & 63;
    row_fwd(srow, bf, 6); __syncthreads();
    row_fwd(srow, bf, 2); __syncthreads();
    for (int idx = t; idx < 512; idx += 128) {
        float2* s = (idx & 256) ? s1 : s0;
        int g = idx & 255;
        C2 a = lds(s,4*g), b = lds(s,4*g+1), c = lds(s,4*g+2), d = lds(s,4*g+3);
        fwd4(a, b, c, d);
        sts(s,4*g,a); sts(s,4*g+1,b); sts(s,4*g+2,c); sts(s,4*g+3,d);
    }
    __syncthreads();
    for (int i = t; i < 1024; i += 128) { r0[i] = s0[SP2(i)]; r1[i] = s1[SP2(i)]; }
}

// ---------------- kB: row FFT + pointwise + row inverse ---------------------
__global__ void __launch_bounds__(128) kB() {
    __shared__ float2 s0[ROWLEN], s1[ROWLEN];
    const int t = threadIdx.x;
    const int b = blockIdx.x & 3, pi = blockIdx.x >> 2, pr = blockIdx.y;
    const int jA = c_jA[pi], jB = c_jB[pi];
    float2* rA = g_B + ((size_t)(b * NPAIR + pr) * 16 + jA) * 1024;
    float2* rB = g_B + ((size_t)(b * NPAIR + pr) * 16 + jB) * 1024;
    const float2* kfA = g_kf + ((size_t)pr * 16 + jA) * 1024;
    const float2* kfB = g_kf + ((size_t)pr * 16 + jB) * 1024;
    for (int i = t; i < 1024; i += 128) {
        s0[SP2(i)] = rA[i];
        s1[SP2(i)] = rB[i];
    }
    __syncthreads();
    float2* srow = (t >= 64) ? s1 : s0;
    const int bf = t & 63;
    row_fwd(srow, bf, 6); __syncthreads();
    row_fwd(srow, bf, 2); __syncthreads();

    if (pi) {
        // cross pair: row A pos p  <->  row B pos 1023-p
        #pragma unroll
        for (int gi = 0; gi < 2; gi++) {
            int g = t + gi * 128, g2 = 255 - g;
            C2 a[4], bb[4], ka[4], kb[4];
            #pragma unroll
            for (int s = 0; s < 4; s++) a[s] = lds(s0, 4*g + s);
            fwd4(a[0], a[1], a[2], a[3]);
            #pragma unroll
            for (int s = 0; s < 4; s++) bb[s] = lds(s1, 4*g2 + s);
            fwd4(bb[0], bb[1], bb[2], bb[3]);
            #pragma unroll
            for (int s = 0; s < 4; s++) {
                float2 u = __ldg(&kfA[4*g + s]);  ka[s] = mkc(u.x, u.y);
                float2 w = __ldg(&kfB[4*g2 + s]); kb[s] = mkc(w.x, w.y);
            }
            #pragma unroll
            for (int s = 0; s < 4; s++) pw(a[s], bb[3-s], ka[s], kb[3-s], a[s], bb[3-s]);
            inv4(a[0], a[1], a[2], a[3]);
            inv4(bb[0], bb[1], bb[2], bb[3]);
            #pragma unroll
            for (int s = 0; s < 4; s++) { sts(s0, 4*g + s, a[s]); sts(s1, 4*g2 + s, bb[s]); }
        }
    } else {
        // row s1 = k1=8: self-mirrored, p <-> 1023-p within the row
        {
            int g = t, g2 = 255 - t;
            C2 a[4], bb[4], ka[4], kb[4];
            #pragma unroll
            for (int s = 0; s < 4; s++) a[s] = lds(s1, 4*g + s);
            fwd4(a[0], a[1], a[2], a[3]);
            #pragma unroll
            for (int s = 0; s < 4; s++) bb[s] = lds(s1, 4*g2 + s);
            fwd4(bb[0], bb[1], bb[2], bb[3]);
            #pragma unroll
            for (int s = 0; s < 4; s++) {
                float2 u = __ldg(&kfB[4*g + s]);  ka[s] = mkc(u.x, u.y);
                float2 w = __ldg(&kfB[4*g2 + s]); kb[s] = mkc(w.x, w.y);
            }
            #pragma unroll
            for (int s = 0; s < 4; s++) pw(a[s], bb[3-s], ka[s], kb[3-s], a[s], bb[3-s]);
            inv4(a[0], a[1], a[2], a[3]);
            inv4(bb[0], bb[1], bb[2], bb[3]);
            #pragma unroll
            for (int s = 0; s < 4; s++) { sts(s1, 4*g + s, a[s]); sts(s1, 4*g2 + s, bb[s]); }
        }
        // row s0 = k1=0: complete forward, frequency-indexed pairing, inverse
        for (int g = t; g < 256; g += 128) {
            C2 a = lds(s0,4*g), b2 = lds(s0,4*g+1), c = lds(s0,4*g+2), d = lds(s0,4*g+3);
            fwd4(a, b2, c, d);
            sts(s0,4*g,a); sts(s0,4*g+1,b2); sts(s0,4*g+2,c); sts(s0,4*g+3,d);
        }
        __syncthreads();
        for (int k2 = t; k2 <= 512; k2 += 128) {
            int p  = drev10(k2);
            int p2 = drev10((1024 - k2) & 1023);
            C2 A = lds(s0, p);
            float2 u = __ldg(&kfA[p]); C2 Cv = mkc(u.x, u.y);
            if (k2 == 0 || k2 == 512) {
                C2 o, dm; pw(A, A, Cv, Cv, o, dm); sts(s0, p, o);
            } else {
                C2 Bv = lds(s0, p2);
                float2 w = __ldg(&kfA[p2]); C2 Dv = mkc(w.x, w.y);
                C2 oF, oN; pw(A, Bv, Cv, Dv, oF, oN);
                sts(s0, p, oF); sts(s0, p2, oN);
            }
        }
        __syncthreads();
        for (int g = t; g < 256; g += 128) {
            C2 a = lds(s0,4*g), b2 = lds(s0,4*g+1), c = lds(s0,4*g+2), d = lds(s0,4*g+3);
            inv4(a, b2, c, d);
            sts(s0,4*g,a); sts(s0,4*g+1,b2); sts(s0,4*g+2,c); sts(s0,4*g+3,d);
        }
    }
    __syncthreads();
    row_inv(srow, bf, 2); __syncthreads();
    row_inv(srow, bf, 6); __syncthreads();
    for (int i = t; i < 1024; i += 128) {
        rA[i] = s0[SP2(i)];
        rB[i] = s1[SP2(i)];
    }
}

// ---------------- kC: 16-pt inverse stage -> y (transposed write) -----------
__global__ void __launch_bounds__(1024) kC(float2* __restrict__ y2) {
    __shared__ float2 tile[32][33];
    const int tx = threadIdx.x & 31, ty = threadIdx.x >> 5;
    const int b = blockIdx.z;
    const int pr0 = blockIdx.x * 32, n20 = blockIdx.y * 32;
    const int n2 = n20 + tx, pr = pr0 + ty;
    C2 v[16];
    #pragma unroll
    for (int j = 0; j < 16; j++) {
        float2 a = g_B[((size_t)(b * NPAIR + pr) * 16 + j) * 1024 + n2];
        v[j] = mkc(a.x, a.y);
    }
    r16_inv(v, twN(n2));
    float2* yb = y2 + (size_t)b * SEQ_L * NPAIR;
    #pragma unroll
    for (int j = 0; j < 8; j++) {
        __syncthreads();
        tile[ty][tx] = make_float2(v[j].x, v[j].y);
        __syncthreads();
        yb[(size_t)(j * 1024 + n20 + ty) * NPAIR + pr0 + tx] = tile[tx][ty];
    }
}

// ------------------------------ launch --------------------------------------
extern "C" void kernel_launch(void* const* d_in, const int* in_sizes, int n_in,
                              void* d_out, int out_size) {
    const float* x    = (const float*)d_in[0];
    const float* filt = (const float*)d_in[1];
    if (n_in >= 2 && in_sizes[0] == 2 * NPAIR * SEQ_L &&
        in_sizes[1] == NBATCH * SEQ_L * 2 * NPAIR) {
        const float* t = x; x = filt; filt = t;
    }
    float* out = (float*)d_out;

    kAf<<<NPAIR, 1024>>>(filt);
    kBf<<<dim3(8, NPAIR), 128>>>();
    kA<<<dim3(16, 32, NBATCH), 1024>>>((const float2*)x);
    kB<<<dim3(32, NPAIR), 128>>>();
    kC<<<dim3(16, 32, NBATCH), 1024>>>((float2*)out);
}

// round 8
// speedup vs baseline: 4.8345x; 1.1176x over previous
#include <cuda_runtime.h>
#include <cuda_fp16.h>
#include <math.h>

#define SEQ_L  8192
#define NPAIR  512
#define NBATCH 4
#define FFT_N  16384
#define ROWLEN 1088                 // 1024 + pad
#define SP2(i) ((i) + ((i) >> 4))

// -------- device globals (no cudaMalloc allowed) ----------------------------
__device__ __half2 g_B[(size_t)NBATCH * NPAIR * 16 * 1024];   // 134 MB staging
__device__ float2  g_kf[(size_t)NPAIR * 16 * 1024];           // 67 MB filter table
__constant__ int c_jA[8] = {0, 1, 4, 5, 6, 7, 8, 9};
__constant__ int c_jB[8] = {2, 3, 15, 14, 13, 12, 11, 10};

// ----------------------------- complex helpers ------------------------------
struct C2 { float x, y; };
__device__ __forceinline__ C2 mkc(float a, float b){ C2 r; r.x=a; r.y=b; return r; }
__device__ __forceinline__ C2 cadd(C2 a, C2 b){ return mkc(a.x+b.x, a.y+b.y); }
__device__ __forceinline__ C2 csub(C2 a, C2 b){ return mkc(a.x-b.x, a.y-b.y); }
__device__ __forceinline__ C2 cmul(C2 a, C2 b){ return mkc(a.x*b.x - a.y*b.y, a.x*b.y + a.y*b.x); }
__device__ __forceinline__ C2 cmulc(C2 a, C2 b){ return mkc(a.x*b.x + a.y*b.y, a.y*b.x - a.x*b.y); }
__device__ __forceinline__ C2 mulni(C2 a){ return mkc(a.y, -a.x); }
__device__ __forceinline__ C2 mulpi(C2 a){ return mkc(-a.y, a.x); }

__device__ __forceinline__ C2 w16c(int n) {
    const float C[10] = {1.f, 0.92387953f, 0.70710678f, 0.38268343f, 0.f,
                         -0.38268343f, -0.70710678f, -0.92387953f, -1.f, -0.92387953f};
    const float S[10] = {0.f, -0.38268343f, -0.70710678f, -0.92387953f, -1.f,
                         -0.92387953f, -0.70710678f, -0.38268343f, 0.f, 0.38268343f};
    return mkc(C[n], S[n]);
}
__device__ __forceinline__ C2 twN(int j) {   // W_16384^j
    float sv, cv; sincospif(-(float)j * (1.0f/8192.0f), &sv, &cv); return mkc(cv, sv);
}
__device__ __forceinline__ C2 tw1k(int j) {  // W_1024^j
    float sv, cv; sincospif(-(float)j * (1.0f/512.0f), &sv, &cv); return mkc(cv, sv);
}
// digit-reverse base-4 of 10-bit index (5 digits). Self-inverse.
__device__ __forceinline__ int drev10(int p) {
    unsigned r = __brev((unsigned)p) >> 22;
    return (int)(((r & 0x155u) << 1) | ((r & 0x2AAu) >> 1));
}

// ---------------- register radix-16 (two fused radix-4 layers) --------------
__device__ __forceinline__ void r16_fwd(C2* v, C2 u1) {
    C2 u2 = cmul(u1,u1);
    C2 u3 = cmul(u2,u1);
    #pragma unroll
    for (int q = 0; q < 4; q++) {
        C2 a=v[q], b=v[q+4], c=v[q+8], d=v[q+12];
        C2 t0=cadd(a,c), t1=csub(a,c), t2=cadd(b,d), t3=mulni(csub(b,d));
        v[q] = cadd(t0,t2);
        C2 o1 = cmul(cadd(t1,t3), u1);
        C2 o2 = cmul(csub(t0,t2), u2);
        C2 o3 = cmul(csub(t1,t3), u3);
        if (q) { o1=cmul(o1,w16c(q)); o2=cmul(o2,w16c(2*q)); o3=cmul(o3,w16c(3*q)); }
        v[q+4]=o1; v[q+8]=o2; v[q+12]=o3;
    }
    C2 u4 = cmul(u2,u2);
    C2 u8 = cmul(u4,u4);
    C2 u12 = cmul(u8,u4);
    #pragma unroll
    for (int s = 0; s < 4; s++) {
        C2 a=v[4*s], b=v[4*s+1], c=v[4*s+2], d=v[4*s+3];
        C2 t0=cadd(a,c), t1=csub(a,c), t2=cadd(b,d), t3=mulni(csub(b,d));
        v[4*s]   = cadd(t0,t2);
        v[4*s+1] = cmul(cadd(t1,t3), u4);
        v[4*s+2] = cmul(csub(t0,t2), u8);
        v[4*s+3] = cmul(csub(t1,t3), u12);
    }
}

__device__ __forceinline__ void r16_fwd_zfold(C2* v, C2 u1) {
    C2 u2 = cmul(u1,u1);
    C2 u3 = cmul(u2,u1);
    #pragma unroll
    for (int q = 0; q < 4; q++) {
        C2 a=v[q], b=v[q+4];
        C2 nb = mulni(b);
        C2 o0 = cadd(a,b);
        C2 o1 = cmul(cadd(a,nb), u1);
        C2 o2 = cmul(csub(a,b), u2);
        C2 o3 = cmul(csub(a,nb), u3);
        if (q) { o1=cmul(o1,w16c(q)); o2=cmul(o2,w16c(2*q)); o3=cmul(o3,w16c(3*q)); }
        v[q]=o0; v[q+4]=o1; v[q+8]=o2; v[q+12]=o3;
    }
    C2 u4 = cmul(u2,u2);
    C2 u8 = cmul(u4,u4);
    C2 u12 = cmul(u8,u4);
    #pragma unroll
    for (int s = 0; s < 4; s++) {
        C2 a=v[4*s], b=v[4*s+1], c=v[4*s+2], d=v[4*s+3];
        C2 t0=cadd(a,c), t1=csub(a,c), t2=cadd(b,d), t3=mulni(csub(b,d));
        v[4*s]   = cadd(t0,t2);
        v[4*s+1] = cmul(cadd(t1,t3), u4);
        v[4*s+2] = cmul(csub(t0,t2), u8);
        v[4*s+3] = cmul(csub(t1,t3), u12);
    }
}

__device__ __forceinline__ void r16_inv(C2* v, C2 u1) {
    C2 u2 = cmul(u1,u1);
    C2 u4 = cmul(u2,u2);
    C2 u8 = cmul(u4,u4);
    C2 u12 = cmul(u8,u4);
    #pragma unroll
    for (int s = 0; s < 4; s++) {
        C2 a = v[4*s];
        C2 b = cmulc(v[4*s+1], u4);
        C2 c = cmulc(v[4*s+2], u8);
        C2 d = cmulc(v[4*s+3], u12);
        C2 p0=cadd(a,c), p1=csub(a,c), p2=cadd(b,d), p3=mulpi(csub(b,d));
        v[4*s]=cadd(p0,p2); v[4*s+1]=cadd(p1,p3); v[4*s+2]=csub(p0,p2); v[4*s+3]=csub(p1,p3);
    }
    C2 u3 = cmul(u2,u1);
    #pragma unroll
    for (int q = 0; q < 4; q++) {
        C2 a = v[q];
        C2 b = cmulc(v[q+4],  u1);
        C2 c = cmulc(v[q+8],  u2);
        C2 d = cmulc(v[q+12], u3);
        if (q) { b=cmulc(b,w16c(q)); c=cmulc(c,w16c(2*q)); d=cmulc(d,w16c(3*q)); }
        C2 p0=cadd(a,c), p1=csub(a,c), p2=cadd(b,d), p3=mulpi(csub(b,d));
        v[q]=cadd(p0,p2); v[q+4]=cadd(p1,p3); v[q+8]=csub(p0,p2); v[q+12]=csub(p1,p3);
    }
}

__device__ __forceinline__ void fwd4(C2& a, C2& b, C2& c, C2& d) {
    C2 t0=cadd(a,c), t1=csub(a,c), t2=cadd(b,d), t3=mulni(csub(b,d));
    a=cadd(t0,t2); b=cadd(t1,t3); c=csub(t0,t2); d=csub(t1,t3);
}
__device__ __forceinline__ void inv4(C2& a, C2& b, C2& c, C2& d) {
    C2 p0=cadd(a,c), p1=csub(a,c), p2=cadd(b,d), p3=mulpi(csub(b,d));
    a=cadd(p0,p2); b=cadd(p1,p3); c=csub(p0,p2); d=csub(p1,p3);
}

// pointwise packed-real product: A=Z[f], Braw=Z[N-f], Cv=Zk[f], Draw=Zk[N-f]
__device__ __forceinline__ void pw(C2 A, C2 Braw, C2 Cv, C2 Draw, C2& outF, C2& outNF) {
    const float s = 1.0f / (4.0f * (float)FFT_N);
    float br = Braw.x, bi = -Braw.y;
    float dr = Draw.x, di = -Draw.y;
    float apbr = A.x + br, apbi = A.y + bi;
    float ambr = A.x - br, ambi = A.y - bi;
    float cpdr = Cv.x + dr, cpdi = Cv.y + di;
    float cmdr = Cv.x - dr, cmdi = Cv.y - di;
    float Pr = apbr * cpdr - apbi * cpdi, Pi = apbr * cpdi + apbi * cpdr;
    float Qr = ambr * cmdr - ambi * cmdi, Qi = ambr * cmdi + ambi * cmdr;
    outF  = mkc((Pr + Qi) * s,  (Pi - Qr) * s);
    outNF = mkc((Pr - Qi) * s, -(Pi + Qr) * s);
}

// --------------------- 1024-point row passes in smem ------------------------
__device__ __forceinline__ C2 lds(const float2* s, int i){ float2 t = s[SP2(i)]; return mkc(t.x,t.y); }
__device__ __forceinline__ void sts(float2* s, int i, C2 v){ s[SP2(i)] = make_float2(v.x,v.y); }

__device__ __forceinline__ void row_fwd(float2* s, int bf, int LM) {
    const int m = 1 << LM;
    const int r = bf & (m - 1);
    const int i0 = ((bf >> LM) << (LM + 4)) + r;
    C2 u1 = tw1k(r << (6 - LM));
    C2 v[16];
    #pragma unroll
    for (int j = 0; j < 16; j++) v[j] = lds(s, i0 + j*m);
    r16_fwd(v, u1);
    #pragma unroll
    for (int j = 0; j < 16; j++) sts(s, i0 + j*m, v[j]);
}
__device__ __forceinline__ void row_inv(float2* s, int bf, int LM) {
    const int m = 1 << LM;
    const int r = bf & (m - 1);
    const int i0 = ((bf >> LM) << (LM + 4)) + r;
    C2 u1 = tw1k(r << (6 - LM));
    C2 v[16];
    #pragma unroll
    for (int j = 0; j < 16; j++) v[j] = lds(s, i0 + j*m);
    r16_inv(v, u1);
    #pragma unroll
    for (int j = 0; j < 16; j++) sts(s, i0 + j*m, v[j]);
}

// ---------------- kA: x -> first 16-pt stage -> g_B (transposed) ------------
__global__ void __launch_bounds__(1024) kA(const float2* __restrict__ x2) {
    __shared__ __half2 tile[32][36];
    const int tx = threadIdx.x & 31, ty = threadIdx.x >> 5;
    const int b = blockIdx.z;
    const int pr0 = blockIdx.x * 32, n20 = blockIdx.y * 32;
    const float2* xb = x2 + (size_t)b * SEQ_L * NPAIR;
    const int n2 = n20 + ty;
    C2 v[16];
    #pragma unroll
    for (int j = 0; j < 8; j++) {
        float2 t = __ldg(&xb[(size_t)(j * 1024 + n2) * NPAIR + pr0 + tx]);
        v[j] = mkc(t.x, t.y);
    }
    r16_fwd_zfold(v, twN(n2));
    #pragma unroll
    for (int j = 0; j < 16; j++) {
        __syncthreads();
        tile[ty][tx] = __floats2half2_rn(v[j].x, v[j].y);
        __syncthreads();
        g_B[((size_t)(b * NPAIR + pr0 + ty) * 16 + j) * 1024 + n20 + tx] = tile[tx][ty];
    }
}

// ---------------- kAf: filt -> first stage -> g_kf (coalesced) --------------
__global__ void __launch_bounds__(1024) kAf(const float* __restrict__ filt) {
    const int n2 = threadIdx.x, pr = blockIdx.x;
    const float* k0 = filt + (size_t)(2 * pr) * SEQ_L;
    const float* k1 = k0 + SEQ_L;
    C2 v[16];
    #pragma unroll
    for (int j = 0; j < 8; j++) {
        int t = j * 1024 + n2;
        v[j] = mkc(k0[t], k1[t]);
    }
    r16_fwd_zfold(v, twN(n2));
    #pragma unroll
    for (int j = 0; j < 16; j++)
        g_kf[((size_t)pr * 16 + j) * 1024 + n2] = make_float2(v[j].x, v[j].y);
}

// ---------------- kBf: forward 1024-FFT of filter rows (in place) -----------
__global__ void __launch_bounds__(128) kBf() {
    __shared__ float2 s0[ROWLEN], s1[ROWLEN];
    const int t = threadIdx.x;
    const int pr = blockIdx.y, j0 = blockIdx.x * 2;
    float2* r0 = g_kf + ((size_t)pr * 16 + j0) * 1024;
    float2* r1 = r0 + 1024;
    for (int i = t; i < 1024; i += 128) { s0[SP2(i)] = r0[i]; s1[SP2(i)] = r1[i]; }
    __syncthreads();
    float2* srow = (t >= 64) ? s1 : s0;
    const int bf = t & 63;
    row_fwd(srow, bf, 6); __syncthreads();
    row_fwd(srow, bf, 2); __syncthreads();
    for (int idx = t; idx < 512; idx += 128) {
        float2* s = (idx & 256) ? s1 : s0;
        int g = idx & 255;
        C2 a = lds(s,4*g), b = lds(s,4*g+1), c = lds(s,4*g+2), d = lds(s,4*g+3);
        fwd4(a, b, c, d);
        sts(s,4*g,a); sts(s,4*g+1,b); sts(s,4*g+2,c); sts(s,4*g+3,d);
    }
    __syncthreads();
    for (int i = t; i < 1024; i += 128) { r0[i] = s0[SP2(i)]; r1[i] = s1[SP2(i)]; }
}

// ---------------- kB: row FFT + pointwise + row inverse ---------------------
__global__ void __launch_bounds__(128, 8) kB() {
    __shared__ float2 s0[ROWLEN], s1[ROWLEN];
    const int t = threadIdx.x;
    const int b = blockIdx.x & 3, pi = blockIdx.x >> 2, pr = blockIdx.y;
    const int jA = c_jA[pi], jB = c_jB[pi];
    __half2* rA = g_B + ((size_t)(b * NPAIR + pr) * 16 + jA) * 1024;
    __half2* rB = g_B + ((size_t)(b * NPAIR + pr) * 16 + jB) * 1024;
    const float2* kfA = g_kf + ((size_t)pr * 16 + jA) * 1024;
    const float2* kfB = g_kf + ((size_t)pr * 16 + jB) * 1024;
    for (int i = t; i < 1024; i += 128) {
        s0[SP2(i)] = __half22float2(rA[i]);
        s1[SP2(i)] = __half22float2(rB[i]);
    }
    __syncthreads();
    float2* srow = (t >= 64) ? s1 : s0;
    const int bf = t & 63;
    row_fwd(srow, bf, 6); __syncthreads();
    row_fwd(srow, bf, 2); __syncthreads();

    if (pi) {
        // cross pair: row A pos p  <->  row B pos 1023-p
        #pragma unroll
        for (int gi = 0; gi < 2; gi++) {
            int g = t + gi * 128, g2 = 255 - g;
            C2 a[4], bb[4], ka[4], kb[4];
            #pragma unroll
            for (int s = 0; s < 4; s++) a[s] = lds(s0, 4*g + s);
            fwd4(a[0], a[1], a[2], a[3]);
            #pragma unroll
            for (int s = 0; s < 4; s++) bb[s] = lds(s1, 4*g2 + s);
            fwd4(bb[0], bb[1], bb[2], bb[3]);
            #pragma unroll
            for (int s = 0; s < 4; s++) {
                float2 u = __ldg(&kfA[4*g + s]);  ka[s] = mkc(u.x, u.y);
                float2 w = __ldg(&kfB[4*g2 + s]); kb[s] = mkc(w.x, w.y);
            }
            #pragma unroll
            for (int s = 0; s < 4; s++) pw(a[s], bb[3-s], ka[s], kb[3-s], a[s], bb[3-s]);
            inv4(a[0], a[1], a[2], a[3]);
            inv4(bb[0], bb[1], bb[2], bb[3]);
            #pragma unroll
            for (int s = 0; s < 4; s++) { sts(s0, 4*g + s, a[s]); sts(s1, 4*g2 + s, bb[s]); }
        }
    } else {
        // row s1 = k1=8: self-mirrored, p <-> 1023-p within the row
        {
            int g = t, g2 = 255 - t;
            C2 a[4], bb[4], ka[4], kb[4];
            #pragma unroll
            for (int s = 0; s < 4; s++) a[s] = lds(s1, 4*g + s);
            fwd4(a[0], a[1], a[2], a[3]);
            #pragma unroll
            for (int s = 0; s < 4; s++) bb[s] = lds(s1, 4*g2 + s);
            fwd4(bb[0], bb[1], bb[2], bb[3]);
            #pragma unroll
            for (int s = 0; s < 4; s++) {
                float2 u = __ldg(&kfB[4*g + s]);  ka[s] = mkc(u.x, u.y);
                float2 w = __ldg(&kfB[4*g2 + s]); kb[s] = mkc(w.x, w.y);
            }
            #pragma unroll
            for (int s = 0; s < 4; s++) pw(a[s], bb[3-s], ka[s], kb[3-s], a[s], bb[3-s]);
            inv4(a[0], a[1], a[2], a[3]);
            inv4(bb[0], bb[1], bb[2], bb[3]);
            #pragma unroll
            for (int s = 0; s < 4; s++) { sts(s1, 4*g + s, a[s]); sts(s1, 4*g2 + s, bb[s]); }
        }
        // row s0 = k1=0: complete forward, frequency-indexed pairing, inverse
        for (int g = t; g < 256; g += 128) {
            C2 a = lds(s0,4*g), b2 = lds(s0,4*g+1), c = lds(s0,4*g+2), d = lds(s0,4*g+3);
            fwd4(a, b2, c, d);
            sts(s0,4*g,a); sts(s0,4*g+1,b2); sts(s0,4*g+2,c); sts(s0,4*g+3,d);
        }
        __syncthreads();
        for (int k2 = t; k2 <= 512; k2 += 128) {
            int p  = drev10(k2);
            int p2 = drev10((1024 - k2) & 1023);
            C2 A = lds(s0, p);
            float2 u = __ldg(&kfA[p]); C2 Cv = mkc(u.x, u.y);
            if (k2 == 0 || k2 == 512) {
                C2 o, dm; pw(A, A, Cv, Cv, o, dm); sts(s0, p, o);
            } else {
                C2 Bv = lds(s0, p2);
                float2 w = __ldg(&kfA[p2]); C2 Dv = mkc(w.x, w.y);
                C2 oF, oN; pw(A, Bv, Cv, Dv, oF, oN);
                sts(s0, p, oF); sts(s0, p2, oN);
            }
        }
        __syncthreads();
        for (int g = t; g < 256; g += 128) {
            C2 a = lds(s0,4*g), b2 = lds(s0,4*g+1), c = lds(s0,4*g+2), d = lds(s0,4*g+3);
            inv4(a, b2, c, d);
            sts(s0,4*g,a); sts(s0,4*g+1,b2); sts(s0,4*g+2,c); sts(s0,4*g+3,d);
        }
    }
    __syncthreads();
    row_inv(srow, bf, 2); __syncthreads();
    row_inv(srow, bf, 6); __syncthreads();
    for (int i = t; i < 1024; i += 128) {
        float2 a = s0[SP2(i)]; rA[i] = __floats2half2_rn(a.x, a.y);
        float2 c = s1[SP2(i)]; rB[i] = __floats2half2_rn(c.x, c.y);
    }
}

// ---------------- kC: 16-pt inverse stage -> y (transposed write) -----------
__global__ void __launch_bounds__(1024) kC(float2* __restrict__ y2) {
    __shared__ float2 tile[32][33];
    const int tx = threadIdx.x & 31, ty = threadIdx.x >> 5;
    const int b = blockIdx.z;
    const int pr0 = blockIdx.x * 32, n20 = blockIdx.y * 32;
    const int n2 = n20 + tx, pr = pr0 + ty;
    C2 v[16];
    #pragma unroll
    for (int j = 0; j < 16; j++) {
        float2 a = __half22float2(g_B[((size_t)(b * NPAIR + pr) * 16 + j) * 1024 + n2]);
        v[j] = mkc(a.x, a.y);
    }
    r16_inv(v, twN(n2));
    float2* yb = y2 + (size_t)b * SEQ_L * NPAIR;
    #pragma unroll
    for (int j = 0; j < 8; j++) {
        __syncthreads();
        tile[ty][tx] = make_float2(v[j].x, v[j].y);
        __syncthreads();
        yb[(size_t)(j * 1024 + n20 + ty) * NPAIR + pr0 + tx] = tile[tx][ty];
    }
}

// ------------------------------ launch --------------------------------------
extern "C" void kernel_launch(void* const* d_in, const int* in_sizes, int n_in,
                              void* d_out, int out_size) {
    const float* x    = (const float*)d_in[0];
    const float* filt = (const float*)d_in[1];
    if (n_in >= 2 && in_sizes[0] == 2 * NPAIR * SEQ_L &&
        in_sizes[1] == NBATCH * SEQ_L * 2 * NPAIR) {
        const float* t = x; x = filt; filt = t;
    }
    float* out = (float*)d_out;

    kAf<<<NPAIR, 1024>>>(filt);
    kBf<<<dim3(8, NPAIR), 128>>>();
    kA<<<dim3(16, 32, NBATCH), 1024>>>((const float2*)x);
    kB<<<dim3(32, NPAIR), 128>>>();
    kC<<<dim3(16, 32, NBATCH), 1024>>>((float2*)out);
}